// round 12
// baseline (speedup 1.0000x reference)
#include <cuda_runtime.h>
#include <cuda_bf16.h>
#include <cstdint>
#include <cstddef>
#include <mma.h>

using namespace nvcuda;

#define B_ 8
#define S_ 2048
#define E_ 1024

// ================= scratch (device globals; allocation-free rule) =================
__device__ __nv_bfloat16 g_Qhi[(size_t)B_ * S_ * E_];
__device__ __nv_bfloat16 g_Qlo[(size_t)B_ * S_ * E_];
__device__ __nv_bfloat16 g_Khi[(size_t)B_ * S_ * E_];
__device__ __nv_bfloat16 g_Klo[(size_t)B_ * S_ * E_];
__device__ __nv_bfloat16 g_Vthi[(size_t)B_ * E_ * S_];  // V transposed: [B, E, S]
__device__ __nv_bfloat16 g_Vtlo[(size_t)B_ * E_ * S_];
__device__ __nv_bfloat16 g_Whi[(size_t)E_ * E_];
__device__ __nv_bfloat16 g_Wlo[(size_t)E_ * E_];
__device__ float         g_scores[(size_t)B_ * S_ * S_];
__device__ __nv_bfloat16 g_Phi[(size_t)B_ * S_ * S_];
__device__ __nv_bfloat16 g_Plo[(size_t)B_ * S_ * S_];
// attn split reuses g_Qhi/g_Qlo (Q dead after GEMM1)

// ================= async-copy helpers =================
__device__ __forceinline__ uint32_t smem_u32(const void* p) {
    uint32_t a;
    asm("{ .reg .u64 t; cvta.to.shared.u64 t, %1; cvt.u32.u64 %0, t; }" : "=r"(a) : "l"(p));
    return a;
}
__device__ __forceinline__ void cp16(uint32_t dst, const void* src) {
    asm volatile("cp.async.cg.shared.global [%0], [%1], 16;" :: "r"(dst), "l"(src) : "memory");
}
__device__ __forceinline__ void cp_commit() { asm volatile("cp.async.commit_group;" ::: "memory"); }
__device__ __forceinline__ void cp_wait1()  { asm volatile("cp.async.wait_group 1;" ::: "memory"); }

// ================= split kernels =================
__global__ void __launch_bounds__(256) split_plane(const float* __restrict__ x,
                                                   __nv_bfloat16* __restrict__ hi,
                                                   __nv_bfloat16* __restrict__ lo, int n8) {
    int i = blockIdx.x * blockDim.x + threadIdx.x;
    if (i >= n8) return;
    const float4* x4 = reinterpret_cast<const float4*>(x) + (size_t)i * 2;
    float4 a = x4[0], b = x4[1];
    float f[8] = {a.x, a.y, a.z, a.w, b.x, b.y, b.z, b.w};
    __nv_bfloat16 h[8], l[8];
#pragma unroll
    for (int j = 0; j < 8; j++) {
        h[j] = __float2bfloat16(f[j]);
        l[j] = __float2bfloat16(f[j] - __bfloat162float(h[j]));
    }
    *reinterpret_cast<uint4*>(hi + (size_t)i * 8) = *reinterpret_cast<const uint4*>(h);
    *reinterpret_cast<uint4*>(lo + (size_t)i * 8) = *reinterpret_cast<const uint4*>(l);
}

// V [B,S,E] f32 -> transposed planes [B,E,S] bf16 hi/lo
__global__ void __launch_bounds__(256) splitT_v(const float* __restrict__ v,
                                                __nv_bfloat16* __restrict__ hi,
                                                __nv_bfloat16* __restrict__ lo) {
    __shared__ float tile[32][33];
    int b = blockIdx.z;
    int s0 = blockIdx.x * 32, e0 = blockIdx.y * 32;
    int tx = threadIdx.x & 31, ty = threadIdx.x >> 5;
    const float* vb = v + (size_t)b * S_ * E_;
#pragma unroll
    for (int k = 0; k < 4; k++)
        tile[ty + 8 * k][tx] = vb[(size_t)(s0 + ty + 8 * k) * E_ + e0 + tx];
    __syncthreads();
    __nv_bfloat16* hb = hi + (size_t)b * E_ * S_;
    __nv_bfloat16* lb = lo + (size_t)b * E_ * S_;
#pragma unroll
    for (int k = 0; k < 4; k++) {
        float f = tile[tx][ty + 8 * k];
        __nv_bfloat16 h = __float2bfloat16(f);
        size_t o = (size_t)(e0 + ty + 8 * k) * S_ + s0 + tx;
        hb[o] = h;
        lb[o] = __float2bfloat16(f - __bfloat162float(h));
    }
}

// ================= softmax * mask -> planar bf16 hi/lo probs (vectorized) ========
__global__ void __launch_bounds__(256) softmax_mask_kernel(
    const float* __restrict__ scores, const float* __restrict__ mask,
    __nv_bfloat16* __restrict__ phi, __nv_bfloat16* __restrict__ plo,
    const int* __restrict__ sc) {
    __shared__ float redmax[8], redsum[8];
    size_t row = blockIdx.x;
    const float4* srow = reinterpret_cast<const float4*>(scores + row * (size_t)S_);
    const float4* mrow = reinterpret_cast<const float4*>(mask + row * (size_t)S_);
    int t = threadIdx.x, lane = t & 31, warp = t >> 5;

    int iv = *sc;
    float denom = (iv == 32) ? 32.0f : __int_as_float(iv);
    float scale = 1.0f / denom;

    float v[8];
#pragma unroll
    for (int j = 0; j < 2; j++) {
        float4 x = srow[t + 256 * j];
        v[4 * j + 0] = x.x * scale; v[4 * j + 1] = x.y * scale;
        v[4 * j + 2] = x.z * scale; v[4 * j + 3] = x.w * scale;
    }
    float m = v[0];
#pragma unroll
    for (int j = 1; j < 8; j++) m = fmaxf(m, v[j]);
#pragma unroll
    for (int o = 16; o; o >>= 1) m = fmaxf(m, __shfl_xor_sync(0xffffffffu, m, o));
    if (lane == 0) redmax[warp] = m;
    __syncthreads();
    float bm = redmax[0];
#pragma unroll
    for (int w = 1; w < 8; w++) bm = fmaxf(bm, redmax[w]);
    float e[8], s = 0.f;
#pragma unroll
    for (int j = 0; j < 8; j++) { e[j] = __expf(v[j] - bm); s += e[j]; }
#pragma unroll
    for (int o = 16; o; o >>= 1) s += __shfl_xor_sync(0xffffffffu, s, o);
    if (lane == 0) redsum[warp] = s;
    __syncthreads();
    float bs = 0.f;
#pragma unroll
    for (int w = 0; w < 8; w++) bs += redsum[w];
    float inv = 1.0f / bs;

    __nv_bfloat16* ph = phi + row * (size_t)S_;
    __nv_bfloat16* pl = plo + row * (size_t)S_;
#pragma unroll
    for (int j = 0; j < 2; j++) {
        float4 mk = mrow[t + 256 * j];
        float mf[4] = {mk.x, mk.y, mk.z, mk.w};
        __nv_bfloat16 h[4], l[4];
#pragma unroll
        for (int q = 0; q < 4; q++) {
            float p = e[4 * j + q] * inv * mf[q];
            h[q] = __float2bfloat16(p);
            l[q] = __float2bfloat16(p - __bfloat162float(h[q]));
        }
        int o = 4 * (t + 256 * j);
        *reinterpret_cast<uint2*>(ph + o) = *reinterpret_cast<const uint2*>(h);
        *reinterpret_cast<uint2*>(pl + o) = *reinterpret_cast<const uint2*>(l);
    }
}

// ================= pipelined split-bf16 WMMA NT GEMM (2 CTAs/SM) =================
// C[M,N] = sum_k A[m,k]*B[n,k]; A/B planar hi/lo bf16, fp32 accum via HMMA.
// Block 128x128x32; 256 threads; 8 warps of 32x64 tiles; 2-stage cp.async;
// 80KB smem -> 2 CTAs resident per SM (cross-CTA latency hiding).
// MODE 0: f32 out. MODE 1: planar bf16 hi/lo out. MODE 2: f32 + bias out.
constexpr int BM = 128, BN = 128, BK = 32;
constexpr int PITCH = 40;                       // BK + 8 pad (bf16) = 80 B/row
constexpr int PLANEB = BM * PITCH * 2;          // 10240 B per plane tile
constexpr int STAGEB = 4 * PLANEB;              // 40960 B
constexpr int STAGES = 2;
constexpr unsigned GSMEM = STAGES * STAGEB;     // 81920 B

template <int MODE>
__global__ void __launch_bounds__(256, 2) gemm_pipe(
    const __nv_bfloat16* __restrict__ Ahi, const __nv_bfloat16* __restrict__ Alo,
    int lda, size_t strA,
    const __nv_bfloat16* __restrict__ Bhi, const __nv_bfloat16* __restrict__ Blo,
    int ldb, size_t strB,
    void* __restrict__ C0, void* __restrict__ C1, int ldc, size_t strC,
    const float* __restrict__ bias, int Kdim) {
    extern __shared__ __nv_bfloat16 smem[];
    const uint32_t sbase = smem_u32(smem);
    const int tid = threadIdx.x;
    const int lane = tid & 31, wid = tid >> 5;
    const int wm = wid >> 1;                 // 0..3  (32-row strips)
    const int wn = wid & 1;                  // 0..1  (64-col strips)
    const int b = blockIdx.z;
    const int m0 = blockIdx.y * BM, n0 = blockIdx.x * BN;

    const __nv_bfloat16* pa[2] = {Ahi + (size_t)b * strA, Alo + (size_t)b * strA};
    const __nv_bfloat16* pb[2] = {Bhi + (size_t)b * strB, Blo + (size_t)b * strB};

    const int niter = Kdim / BK;

    // stage loader: 4 planes x (128 rows x 32 bf16 = 64B) with cp.async 16B chunks
    auto load_stage = [&](int j) {
        const int k0 = j * BK;
        const uint32_t sb = sbase + (j % STAGES) * STAGEB;
#pragma unroll
        for (int p = 0; p < 4; p++) {
            const __nv_bfloat16* src = (p < 2) ? pa[p] : pb[p - 2];
            const int r0 = (p < 2) ? m0 : n0;
            const int ld = (p < 2) ? lda : ldb;
#pragma unroll
            for (int it = 0; it < 2; it++) {
                int id = tid + it * 256;          // 512 chunks per plane
                int r = id >> 2, c = id & 3;      // 128 rows x 4 x 16B
                uint32_t dst = sb + (uint32_t)p * PLANEB + (uint32_t)(r * (PITCH * 2) + c * 16);
                cp16(dst, src + (size_t)(r0 + r) * ld + k0 + c * 8);
            }
        }
    };

    wmma::fragment<wmma::accumulator, 16, 16, 16, float> acc[2][4];
#pragma unroll
    for (int i = 0; i < 2; i++)
#pragma unroll
        for (int j = 0; j < 4; j++) wmma::fill_fragment(acc[i][j], 0.f);

    // prologue
    load_stage(0); cp_commit();
    load_stage(1); cp_commit();

    for (int i = 0; i < niter; i++) {
        cp_wait1();          // stage i resident (load of i+1 may still be in flight)
        __syncthreads();

        // compute stage i (overlaps the in-flight load of stage i+1)
        const __nv_bfloat16* As_hi = smem + (size_t)(i % STAGES) * (STAGEB / 2);
        const __nv_bfloat16* As_lo = As_hi + PLANEB / 2;
        const __nv_bfloat16* Bs_hi = As_hi + 2 * (PLANEB / 2);
        const __nv_bfloat16* Bs_lo = As_hi + 3 * (PLANEB / 2);

#pragma unroll
        for (int kk = 0; kk < BK; kk += 16) {
            wmma::fragment<wmma::matrix_a, 16, 16, 16, __nv_bfloat16, wmma::row_major> ah[2], al[2];
#pragma unroll
            for (int x = 0; x < 2; x++) {
                int row = wm * 32 + x * 16;
                wmma::load_matrix_sync(ah[x], As_hi + row * PITCH + kk, PITCH);
                wmma::load_matrix_sync(al[x], As_lo + row * PITCH + kk, PITCH);
            }
            wmma::fragment<wmma::matrix_b, 16, 16, 16, __nv_bfloat16, wmma::col_major> bh[4], bl[4];
#pragma unroll
            for (int y = 0; y < 4; y++) {
                int col = wn * 64 + y * 16;
                wmma::load_matrix_sync(bh[y], Bs_hi + col * PITCH + kk, PITCH);
                wmma::load_matrix_sync(bl[y], Bs_lo + col * PITCH + kk, PITCH);
            }
            // phase-ordered issue (per-acc order hh -> hl -> lh preserved)
#pragma unroll
            for (int x = 0; x < 2; x++)
#pragma unroll
                for (int y = 0; y < 4; y++)
                    wmma::mma_sync(acc[x][y], ah[x], bh[y], acc[x][y]);
#pragma unroll
            for (int x = 0; x < 2; x++)
#pragma unroll
                for (int y = 0; y < 4; y++)
                    wmma::mma_sync(acc[x][y], ah[x], bl[y], acc[x][y]);
#pragma unroll
            for (int x = 0; x < 2; x++)
#pragma unroll
                for (int y = 0; y < 4; y++)
                    wmma::mma_sync(acc[x][y], al[x], bh[y], acc[x][y]);
        }
        __syncthreads();     // compute done before overwriting this buffer

        // prefetch stage i+2 into the buffer just freed
        if (i + 2 < niter) load_stage(i + 2);
        cp_commit();         // (possibly empty) keeps wait_group accounting uniform
    }

    // ---------------- epilogue ----------------
    if (MODE == 0) {
        float* C = reinterpret_cast<float*>(C0) + (size_t)b * strC;
#pragma unroll
        for (int x = 0; x < 2; x++)
#pragma unroll
            for (int y = 0; y < 4; y++) {
                int gr = m0 + wm * 32 + x * 16;
                int gc = n0 + wn * 64 + y * 16;
                wmma::store_matrix_sync(C + (size_t)gr * ldc + gc, acc[x][y], ldc,
                                        wmma::mem_row_major);
            }
    } else {
        // per-warp 16x72 f32 staging slab (stage buffers dead after final barrier)
        float* stage = reinterpret_cast<float*>(smem) + wid * (16 * 72);
        int wr0 = m0 + wm * 32, wc0 = n0 + wn * 64;
#pragma unroll
        for (int x = 0; x < 2; x++) {
#pragma unroll
            for (int y = 0; y < 4; y++)
                wmma::store_matrix_sync(stage + y * 16, acc[x][y], 72, wmma::mem_row_major);
            __syncwarp();
#pragma unroll
            for (int it = 0; it < 8; it++) {
                int idx = lane + it * 32;
                int r = idx >> 4, c = (idx & 15) << 2;
                float4 v = *reinterpret_cast<float4*>(stage + r * 72 + c);
                int gr = wr0 + x * 16 + r, gc = wc0 + c;
                if (MODE == 2) {
                    v.x += bias[gc]; v.y += bias[gc + 1];
                    v.z += bias[gc + 2]; v.w += bias[gc + 3];
                    float* C = reinterpret_cast<float*>(C0);
                    *reinterpret_cast<float4*>(C + (size_t)gr * ldc + gc) = v;
                } else {
                    __nv_bfloat16* Ch = reinterpret_cast<__nv_bfloat16*>(C0) + (size_t)b * strC;
                    __nv_bfloat16* Cl = reinterpret_cast<__nv_bfloat16*>(C1) + (size_t)b * strC;
                    float f[4] = {v.x, v.y, v.z, v.w};
                    __nv_bfloat16 h[4], l[4];
#pragma unroll
                    for (int q = 0; q < 4; q++) {
                        h[q] = __float2bfloat16(f[q]);
                        l[q] = __float2bfloat16(f[q] - __bfloat162float(h[q]));
                    }
                    size_t o = (size_t)gr * ldc + gc;
                    *reinterpret_cast<uint2*>(Ch + o) = *reinterpret_cast<const uint2*>(h);
                    *reinterpret_cast<uint2*>(Cl + o) = *reinterpret_cast<const uint2*>(l);
                }
            }
            __syncwarp();
        }
    }
}

// ================= launch =================
extern "C" void kernel_launch(void* const* d_in, const int* in_sizes, int n_in,
                              void* d_out, int out_size) {
    const float* Q    = (const float*)d_in[0];
    const float* Kx   = (const float*)d_in[1];
    const float* V    = (const float*)d_in[2];
    const float* mask = (const float*)d_in[3];
    const float* W    = (const float*)d_in[4];
    const float* bias = (const float*)d_in[5];
    const int*   inv  = (const int*)d_in[6];

    void *pQh, *pQl, *pKh, *pKl, *pVh, *pVl, *pWh, *pWl, *pS, *pPh, *pPl;
    cudaGetSymbolAddress(&pQh, g_Qhi);  cudaGetSymbolAddress(&pQl, g_Qlo);
    cudaGetSymbolAddress(&pKh, g_Khi);  cudaGetSymbolAddress(&pKl, g_Klo);
    cudaGetSymbolAddress(&pVh, g_Vthi); cudaGetSymbolAddress(&pVl, g_Vtlo);
    cudaGetSymbolAddress(&pWh, g_Whi);  cudaGetSymbolAddress(&pWl, g_Wlo);
    cudaGetSymbolAddress(&pS, g_scores);
    cudaGetSymbolAddress(&pPh, g_Phi);  cudaGetSymbolAddress(&pPl, g_Plo);

    __nv_bfloat16 *Qh = (__nv_bfloat16*)pQh, *Ql = (__nv_bfloat16*)pQl;
    __nv_bfloat16 *Kh = (__nv_bfloat16*)pKh, *Kl = (__nv_bfloat16*)pKl;
    __nv_bfloat16 *Vh = (__nv_bfloat16*)pVh, *Vl = (__nv_bfloat16*)pVl;
    __nv_bfloat16 *Wh = (__nv_bfloat16*)pWh, *Wl = (__nv_bfloat16*)pWl;
    float* Sc = (float*)pS;
    __nv_bfloat16 *Ph = (__nv_bfloat16*)pPh, *Pl = (__nv_bfloat16*)pPl;
    __nv_bfloat16 *Ath = Qh, *Atl = Ql;  // attn reuses Q planes

    cudaFuncSetAttribute(gemm_pipe<0>, cudaFuncAttributeMaxDynamicSharedMemorySize, GSMEM);
    cudaFuncSetAttribute(gemm_pipe<1>, cudaFuncAttributeMaxDynamicSharedMemorySize, GSMEM);
    cudaFuncSetAttribute(gemm_pipe<2>, cudaFuncAttributeMaxDynamicSharedMemorySize, GSMEM);

    const int n8 = B_ * S_ * E_ / 8;
    const int w8 = E_ * E_ / 8;

    // launch order keeps GEMM1 at index 3 (the ncu capture slot)
    split_plane<<<(n8 + 255) / 256, 256>>>(Q, Qh, Ql, n8);     // 0
    split_plane<<<(n8 + 255) / 256, 256>>>(Kx, Kh, Kl, n8);    // 1
    split_plane<<<(w8 + 255) / 256, 256>>>(W, Wh, Wl, w8);     // 2

    // GEMM1: scores = Q @ K^T  [M=S, N=S, K=E]                   3
    dim3 g1(S_ / BN, S_ / BM, B_);
    gemm_pipe<0><<<g1, 256, GSMEM>>>(Qh, Ql, E_, (size_t)S_ * E_,
                                     Kh, Kl, E_, (size_t)S_ * E_,
                                     Sc, nullptr, S_, (size_t)S_ * S_, nullptr, E_);

    // V split (needed only by GEMM2)                              4
    dim3 gt(S_ / 32, E_ / 32, B_);
    splitT_v<<<gt, 256>>>(V, Vh, Vl);

    // softmax * mask -> planar probs                              5
    softmax_mask_kernel<<<B_ * S_, 256>>>(Sc, mask, Ph, Pl, inv);

    // GEMM2: attn = P @ Vt^T   [M=S, N=E, K=S]                    6
    dim3 g2(E_ / BN, S_ / BM, B_);
    gemm_pipe<1><<<g2, 256, GSMEM>>>(Ph, Pl, S_, (size_t)S_ * S_,
                                     Vh, Vl, S_, (size_t)E_ * S_,
                                     Ath, Atl, E_, (size_t)S_ * E_, nullptr, S_);

    // GEMM3: out = attn @ W^T + bias  [M=B*S, N=E, K=E]           7
    dim3 g3(E_ / BN, (B_ * S_) / BM, 1);
    gemm_pipe<2><<<g3, 256, GSMEM>>>(Ath, Atl, E_, 0,
                                     Wh, Wl, E_, 0,
                                     d_out, nullptr, E_, 0, bias, E_);
}

// round 13
// speedup vs baseline: 3.5715x; 3.5715x over previous
#include <cuda_runtime.h>
#include <cuda_fp16.h>
#include <cstdint>
#include <cstddef>
#include <mma.h>

using namespace nvcuda;

#define B_ 8
#define S_ 2048
#define E_ 1024

// ================= scratch (device globals; allocation-free rule) =================
__device__ __half g_Qh[(size_t)B_ * S_ * E_];
__device__ __half g_Kh[(size_t)B_ * S_ * E_];
__device__ __half g_Vt[(size_t)B_ * E_ * S_];   // V transposed [B,E,S]
__device__ __half g_Wh[(size_t)E_ * E_];
__device__ float  g_scores[(size_t)B_ * S_ * S_];
__device__ __half g_P[(size_t)B_ * S_ * S_];
__device__ __half g_At[(size_t)B_ * S_ * E_];   // attn fp16

// ================= async-copy helpers =================
__device__ __forceinline__ uint32_t smem_u32(const void* p) {
    uint32_t a;
    asm("{ .reg .u64 t; cvta.to.shared.u64 t, %1; cvt.u32.u64 %0, t; }" : "=r"(a) : "l"(p));
    return a;
}
__device__ __forceinline__ void cp16(uint32_t dst, const void* src) {
    asm volatile("cp.async.cg.shared.global [%0], [%1], 16;" :: "r"(dst), "l"(src) : "memory");
}
__device__ __forceinline__ void cp_commit() { asm volatile("cp.async.commit_group;" ::: "memory"); }
__device__ __forceinline__ void cp_wait2()  { asm volatile("cp.async.wait_group 2;" ::: "memory"); }

// ================= prep kernels =================
__global__ void __launch_bounds__(256) cvt_half(const float* __restrict__ x,
                                                __half* __restrict__ y, int n8) {
    int i = blockIdx.x * blockDim.x + threadIdx.x;
    if (i >= n8) return;
    const float4* x4 = reinterpret_cast<const float4*>(x) + (size_t)i * 2;
    float4 a = x4[0], b = x4[1];
    float f[8] = {a.x, a.y, a.z, a.w, b.x, b.y, b.z, b.w};
    __half h[8];
#pragma unroll
    for (int j = 0; j < 8; j++) h[j] = __float2half_rn(f[j]);
    *reinterpret_cast<uint4*>(y + (size_t)i * 8) = *reinterpret_cast<const uint4*>(h);
}

// V [B,S,E] f32 -> [B,E,S] fp16
__global__ void __launch_bounds__(256) transpose_v(const float* __restrict__ v,
                                                   __half* __restrict__ vt) {
    __shared__ float tile[32][33];
    int b = blockIdx.z;
    int s0 = blockIdx.x * 32, e0 = blockIdx.y * 32;
    int tx = threadIdx.x & 31, ty = threadIdx.x >> 5;
    const float* vb = v + (size_t)b * S_ * E_;
#pragma unroll
    for (int k = 0; k < 4; k++)
        tile[ty + 8 * k][tx] = vb[(size_t)(s0 + ty + 8 * k) * E_ + e0 + tx];
    __syncthreads();
    __half* ob = vt + (size_t)b * E_ * S_;
#pragma unroll
    for (int k = 0; k < 4; k++)
        ob[(size_t)(e0 + ty + 8 * k) * S_ + s0 + tx] = __float2half_rn(tile[tx][ty + 8 * k]);
}

// ================= softmax * mask -> fp16 probs =================
__global__ void __launch_bounds__(256) softmax_mask_kernel(
    const float* __restrict__ scores, const float* __restrict__ mask,
    __half* __restrict__ probs, const int* __restrict__ sc) {
    __shared__ float redmax[8], redsum[8];
    size_t row = blockIdx.x;
    const float4* srow = reinterpret_cast<const float4*>(scores + row * (size_t)S_);
    const float4* mrow = reinterpret_cast<const float4*>(mask + row * (size_t)S_);
    int t = threadIdx.x, lane = t & 31, warp = t >> 5;

    int iv = *sc;
    float denom = (iv == 32) ? 32.0f : __int_as_float(iv);
    float scale = 1.0f / denom;

    float v[8];
#pragma unroll
    for (int j = 0; j < 2; j++) {
        float4 x = srow[t + 256 * j];
        v[4 * j + 0] = x.x * scale; v[4 * j + 1] = x.y * scale;
        v[4 * j + 2] = x.z * scale; v[4 * j + 3] = x.w * scale;
    }
    float m = v[0];
#pragma unroll
    for (int j = 1; j < 8; j++) m = fmaxf(m, v[j]);
#pragma unroll
    for (int o = 16; o; o >>= 1) m = fmaxf(m, __shfl_xor_sync(0xffffffffu, m, o));
    if (lane == 0) redmax[warp] = m;
    __syncthreads();
    float bm = redmax[0];
#pragma unroll
    for (int w = 1; w < 8; w++) bm = fmaxf(bm, redmax[w]);
    float e[8], s = 0.f;
#pragma unroll
    for (int j = 0; j < 8; j++) { e[j] = __expf(v[j] - bm); s += e[j]; }
#pragma unroll
    for (int o = 16; o; o >>= 1) s += __shfl_xor_sync(0xffffffffu, s, o);
    if (lane == 0) redsum[warp] = s;
    __syncthreads();
    float bs = 0.f;
#pragma unroll
    for (int w = 0; w < 8; w++) bs += redsum[w];
    float inv = 1.0f / bs;

    __half* prow = probs + row * (size_t)S_;
#pragma unroll
    for (int j = 0; j < 2; j++) {
        float4 mk = mrow[t + 256 * j];
        float mf[4] = {mk.x, mk.y, mk.z, mk.w};
        __half h[4];
#pragma unroll
        for (int q = 0; q < 4; q++)
            h[q] = __float2half_rn(e[4 * j + q] * inv * mf[q]);
        *reinterpret_cast<uint2*>(prow + 4 * (t + 256 * j)) =
            *reinterpret_cast<const uint2*>(h);
    }
}

// ================= pipelined fp16 WMMA NT GEMM (4-stage, 1 barrier/iter) =========
// C[M,N] = sum_k A[m,k]*B[n,k]; fp16 in, fp32 accum via HMMA.
// MODE 0: f32 out. MODE 1: fp16 out. MODE 2: f32 + bias out.
constexpr int BM = 128, BN = 128, BK = 64;
constexpr int PITCH = 72;                       // BK + 8 pad (halfs) = 144 B/row
constexpr int PLANEB = BM * PITCH * 2;          // 18432 B per operand tile
constexpr int STAGEB = 2 * PLANEB;              // A + B = 36864 B
constexpr int STAGES = 4;
constexpr unsigned GSMEM = STAGES * STAGEB;     // 147456 B -> 1 CTA/SM

template <int MODE>
__global__ void __launch_bounds__(256) gemm_h(
    const __half* __restrict__ A, int lda, size_t strA,
    const __half* __restrict__ Bm, int ldb, size_t strB,
    void* __restrict__ C, int ldc, size_t strC,
    const float* __restrict__ bias, int Kdim) {
    extern __shared__ __half smem[];
    const uint32_t sbase = smem_u32(smem);
    const int tid = threadIdx.x;
    const int lane = tid & 31, wid = tid >> 5;
    const int wm = wid >> 1;                 // 0..3  (32-row strips)
    const int wn = wid & 1;                  // 0..1  (64-col strips)
    const int b = blockIdx.z;
    const int m0 = blockIdx.y * BM, n0 = blockIdx.x * BN;

    const __half* Ab = A + (size_t)b * strA;
    const __half* Bb = Bm + (size_t)b * strB;

    const int niter = Kdim / BK;

    // stage loader: 2 planes x (128 rows x 64 halfs = 128B/row) cp.async 16B chunks
    auto load_stage = [&](int j) {
        const int k0 = j * BK;
        const uint32_t sb = sbase + (j % STAGES) * STAGEB;
#pragma unroll
        for (int it = 0; it < 4; it++) {
            int id = tid + it * 256;             // 1024 chunks
            int r = id >> 3, c = id & 7;         // 128 rows x 8 x 16B
            uint32_t dst = sb + (uint32_t)(r * (PITCH * 2) + c * 16);
            cp16(dst, Ab + (size_t)(m0 + r) * lda + k0 + c * 8);
        }
#pragma unroll
        for (int it = 0; it < 4; it++) {
            int id = tid + it * 256;
            int r = id >> 3, c = id & 7;
            uint32_t dst = sb + (uint32_t)PLANEB + (uint32_t)(r * (PITCH * 2) + c * 16);
            cp16(dst, Bb + (size_t)(n0 + r) * ldb + k0 + c * 8);
        }
    };

    wmma::fragment<wmma::accumulator, 16, 16, 16, float> acc[2][4];
#pragma unroll
    for (int i = 0; i < 2; i++)
#pragma unroll
        for (int j = 0; j < 4; j++) wmma::fill_fragment(acc[i][j], 0.f);

    // prologue: 3 stages in flight
    load_stage(0); cp_commit();
    load_stage(1); cp_commit();
    load_stage(2); cp_commit();

    for (int i = 0; i < niter; i++) {
        cp_wait2();          // stage i resident (i+1, i+2 may be in flight)
        __syncthreads();     // stage i visible + all warps done computing i-1

        // prefetch stage i+3 into buffer (i+3)%4 = (i-1)%4 (dead: see barrier above)
        if (i + 3 < niter) load_stage(i + 3);
        cp_commit();

        // compute stage i
        const __half* As = smem + (size_t)(i % STAGES) * (STAGEB / 2);
        const __half* Bs = As + PLANEB / 2;

#pragma unroll
        for (int kk = 0; kk < BK; kk += 16) {
            wmma::fragment<wmma::matrix_a, 16, 16, 16, __half, wmma::row_major> af[2];
#pragma unroll
            for (int x = 0; x < 2; x++) {
                int row = wm * 32 + x * 16;
                wmma::load_matrix_sync(af[x], As + row * PITCH + kk, PITCH);
            }
            wmma::fragment<wmma::matrix_b, 16, 16, 16, __half, wmma::col_major> bf[4];
#pragma unroll
            for (int y = 0; y < 4; y++) {
                int col = wn * 64 + y * 16;
                wmma::load_matrix_sync(bf[y], Bs + col * PITCH + kk, PITCH);
            }
#pragma unroll
            for (int x = 0; x < 2; x++)
#pragma unroll
                for (int y = 0; y < 4; y++)
                    wmma::mma_sync(acc[x][y], af[x], bf[y], acc[x][y]);
        }
        // no trailing barrier: next iteration's top barrier provides the ordering
    }

    __syncthreads();   // all compute done before epilogue reuses stage smem

    // ---------------- epilogue ----------------
    if (MODE == 0) {
        float* Cb = reinterpret_cast<float*>(C) + (size_t)b * strC;
#pragma unroll
        for (int x = 0; x < 2; x++)
#pragma unroll
            for (int y = 0; y < 4; y++) {
                int gr = m0 + wm * 32 + x * 16;
                int gc = n0 + wn * 64 + y * 16;
                wmma::store_matrix_sync(Cb + (size_t)gr * ldc + gc, acc[x][y], ldc,
                                        wmma::mem_row_major);
            }
    } else {
        float* stage = reinterpret_cast<float*>(smem) + wid * (32 * 72);
#pragma unroll
        for (int x = 0; x < 2; x++)
#pragma unroll
            for (int y = 0; y < 4; y++)
                wmma::store_matrix_sync(stage + x * 16 * 72 + y * 16, acc[x][y], 72,
                                        wmma::mem_row_major);
        __syncwarp();
        int wr0 = m0 + wm * 32, wc0 = n0 + wn * 64;
#pragma unroll
        for (int it = 0; it < 16; it++) {
            int idx = lane + it * 32;
            int r = idx >> 4, c = (idx & 15) << 2;
            float4 v = *reinterpret_cast<float4*>(stage + r * 72 + c);
            int gr = wr0 + r, gc = wc0 + c;
            if (MODE == 2) {
                v.x += bias[gc]; v.y += bias[gc + 1];
                v.z += bias[gc + 2]; v.w += bias[gc + 3];
                float* Cb = reinterpret_cast<float*>(C);
                *reinterpret_cast<float4*>(Cb + (size_t)gr * ldc + gc) = v;
            } else {  // MODE 1: fp16 out
                __half* Cb = reinterpret_cast<__half*>(C) + (size_t)b * strC;
                __half h[4] = {__float2half_rn(v.x), __float2half_rn(v.y),
                               __float2half_rn(v.z), __float2half_rn(v.w)};
                *reinterpret_cast<uint2*>(Cb + (size_t)gr * ldc + gc) =
                    *reinterpret_cast<const uint2*>(h);
            }
        }
    }
}

// ================= launch =================
extern "C" void kernel_launch(void* const* d_in, const int* in_sizes, int n_in,
                              void* d_out, int out_size) {
    const float* Q    = (const float*)d_in[0];
    const float* Kx   = (const float*)d_in[1];
    const float* V    = (const float*)d_in[2];
    const float* mask = (const float*)d_in[3];
    const float* W    = (const float*)d_in[4];
    const float* bias = (const float*)d_in[5];
    const int*   inv  = (const int*)d_in[6];

    void *pQ, *pK, *pVt, *pW, *pS, *pP, *pA;
    cudaGetSymbolAddress(&pQ, g_Qh);
    cudaGetSymbolAddress(&pK, g_Kh);
    cudaGetSymbolAddress(&pVt, g_Vt);
    cudaGetSymbolAddress(&pW, g_Wh);
    cudaGetSymbolAddress(&pS, g_scores);
    cudaGetSymbolAddress(&pP, g_P);
    cudaGetSymbolAddress(&pA, g_At);

    __half *Qh = (__half*)pQ, *Kh = (__half*)pK, *Vt = (__half*)pVt, *Wh = (__half*)pW;
    float* Sc = (float*)pS;
    __half *P = (__half*)pP, *At = (__half*)pA;

    cudaFuncSetAttribute(gemm_h<0>, cudaFuncAttributeMaxDynamicSharedMemorySize, GSMEM);
    cudaFuncSetAttribute(gemm_h<1>, cudaFuncAttributeMaxDynamicSharedMemorySize, GSMEM);
    cudaFuncSetAttribute(gemm_h<2>, cudaFuncAttributeMaxDynamicSharedMemorySize, GSMEM);

    const int n8 = B_ * S_ * E_ / 8;
    const int w8 = E_ * E_ / 8;

    // launch order keeps GEMM1 at index 3 (the ncu capture slot)
    cvt_half<<<(n8 + 255) / 256, 256>>>(Q, Qh, n8);            // 0
    cvt_half<<<(n8 + 255) / 256, 256>>>(Kx, Kh, n8);           // 1
    cvt_half<<<(w8 + 255) / 256, 256>>>(W, Wh, w8);            // 2

    // GEMM1: scores = Q @ K^T  [M=S, N=S, K=E]                   3
    dim3 g1(S_ / BN, S_ / BM, B_);
    gemm_h<0><<<g1, 256, GSMEM>>>(Qh, E_, (size_t)S_ * E_,
                                  Kh, E_, (size_t)S_ * E_,
                                  Sc, S_, (size_t)S_ * S_, nullptr, E_);

    // V transpose (needed only by GEMM2)                          4
    dim3 gt(S_ / 32, E_ / 32, B_);
    transpose_v<<<gt, 256>>>(V, Vt);

    // softmax * mask -> fp16 probs                                5
    softmax_mask_kernel<<<B_ * S_, 256>>>(Sc, mask, P, inv);

    // GEMM2: attn = P @ Vt^T   [M=S, N=E, K=S]                    6
    dim3 g2(E_ / BN, S_ / BM, B_);
    gemm_h<1><<<g2, 256, GSMEM>>>(P, S_, (size_t)S_ * S_,
                                  Vt, S_, (size_t)E_ * S_,
                                  At, E_, (size_t)S_ * E_, nullptr, S_);

    // GEMM3: out = attn @ W^T + bias  [M=B*S, N=E, K=E]           7
    dim3 g3(E_ / BN, (B_ * S_) / BM, 1);
    gemm_h<2><<<g3, 256, GSMEM>>>(At, E_, 0,
                                  Wh, E_, 0,
                                  d_out, E_, 0, bias, E_);
}

// round 14
// speedup vs baseline: 3.6868x; 1.0323x over previous
#include <cuda_runtime.h>
#include <cuda_fp16.h>
#include <cstdint>
#include <cstddef>
#include <mma.h>

using namespace nvcuda;

#define B_ 8
#define S_ 2048
#define E_ 1024

// ================= scratch (device globals; allocation-free rule) =================
__device__ __half g_Qh[(size_t)B_ * S_ * E_];
__device__ __half g_Kh[(size_t)B_ * S_ * E_];
__device__ __half g_Vt[(size_t)B_ * E_ * S_];   // V transposed [B,E,S]
__device__ __half g_Wh[(size_t)E_ * E_];
__device__ float  g_scores[(size_t)B_ * S_ * S_];
__device__ __half g_P[(size_t)B_ * S_ * S_];
__device__ __half g_At[(size_t)B_ * S_ * E_];   // attn fp16

// ================= async-copy helpers =================
__device__ __forceinline__ uint32_t smem_u32(const void* p) {
    uint32_t a;
    asm("{ .reg .u64 t; cvta.to.shared.u64 t, %1; cvt.u32.u64 %0, t; }" : "=r"(a) : "l"(p));
    return a;
}
__device__ __forceinline__ void cp16(uint32_t dst, const void* src) {
    asm volatile("cp.async.cg.shared.global [%0], [%1], 16;" :: "r"(dst), "l"(src) : "memory");
}
__device__ __forceinline__ void cp_commit() { asm volatile("cp.async.commit_group;" ::: "memory"); }
__device__ __forceinline__ void cp_wait2()  { asm volatile("cp.async.wait_group 2;" ::: "memory"); }

// ================= prep kernels =================
__global__ void __launch_bounds__(256) cvt_half(const float* __restrict__ x,
                                                __half* __restrict__ y, int n8) {
    int i = blockIdx.x * blockDim.x + threadIdx.x;
    if (i >= n8) return;
    const float4* x4 = reinterpret_cast<const float4*>(x) + (size_t)i * 2;
    float4 a = x4[0], b = x4[1];
    float f[8] = {a.x, a.y, a.z, a.w, b.x, b.y, b.z, b.w};
    __half h[8];
#pragma unroll
    for (int j = 0; j < 8; j++) h[j] = __float2half_rn(f[j]);
    *reinterpret_cast<uint4*>(y + (size_t)i * 8) = *reinterpret_cast<const uint4*>(h);
}

// V [B,S,E] f32 -> [B,E,S] fp16
__global__ void __launch_bounds__(256) transpose_v(const float* __restrict__ v,
                                                   __half* __restrict__ vt) {
    __shared__ float tile[32][33];
    int b = blockIdx.z;
    int s0 = blockIdx.x * 32, e0 = blockIdx.y * 32;
    int tx = threadIdx.x & 31, ty = threadIdx.x >> 5;
    const float* vb = v + (size_t)b * S_ * E_;
#pragma unroll
    for (int k = 0; k < 4; k++)
        tile[ty + 8 * k][tx] = vb[(size_t)(s0 + ty + 8 * k) * E_ + e0 + tx];
    __syncthreads();
    __half* ob = vt + (size_t)b * E_ * S_;
#pragma unroll
    for (int k = 0; k < 4; k++)
        ob[(size_t)(e0 + ty + 8 * k) * S_ + s0 + tx] = __float2half_rn(tile[tx][ty + 8 * k]);
}

// ================= softmax * mask -> fp16 probs =================
__global__ void __launch_bounds__(256) softmax_mask_kernel(
    const float* __restrict__ scores, const float* __restrict__ mask,
    __half* __restrict__ probs, const int* __restrict__ sc) {
    __shared__ float redmax[8], redsum[8];
    size_t row = blockIdx.x;
    const float4* srow = reinterpret_cast<const float4*>(scores + row * (size_t)S_);
    const float4* mrow = reinterpret_cast<const float4*>(mask + row * (size_t)S_);
    int t = threadIdx.x, lane = t & 31, warp = t >> 5;

    int iv = *sc;
    float denom = (iv == 32) ? 32.0f : __int_as_float(iv);
    float scale = 1.0f / denom;

    float v[8];
#pragma unroll
    for (int j = 0; j < 2; j++) {
        float4 x = srow[t + 256 * j];
        v[4 * j + 0] = x.x * scale; v[4 * j + 1] = x.y * scale;
        v[4 * j + 2] = x.z * scale; v[4 * j + 3] = x.w * scale;
    }
    float m = v[0];
#pragma unroll
    for (int j = 1; j < 8; j++) m = fmaxf(m, v[j]);
#pragma unroll
    for (int o = 16; o; o >>= 1) m = fmaxf(m, __shfl_xor_sync(0xffffffffu, m, o));
    if (lane == 0) redmax[warp] = m;
    __syncthreads();
    float bm = redmax[0];
#pragma unroll
    for (int w = 1; w < 8; w++) bm = fmaxf(bm, redmax[w]);
    float e[8], s = 0.f;
#pragma unroll
    for (int j = 0; j < 8; j++) { e[j] = __expf(v[j] - bm); s += e[j]; }
#pragma unroll
    for (int o = 16; o; o >>= 1) s += __shfl_xor_sync(0xffffffffu, s, o);
    if (lane == 0) redsum[warp] = s;
    __syncthreads();
    float bs = 0.f;
#pragma unroll
    for (int w = 0; w < 8; w++) bs += redsum[w];
    float inv = 1.0f / bs;

    __half* prow = probs + row * (size_t)S_;
#pragma unroll
    for (int j = 0; j < 2; j++) {
        float4 mk = mrow[t + 256 * j];
        float mf[4] = {mk.x, mk.y, mk.z, mk.w};
        __half h[4];
#pragma unroll
        for (int q = 0; q < 4; q++)
            h[q] = __float2half_rn(e[4 * j + q] * inv * mf[q]);
        *reinterpret_cast<uint2*>(prow + 4 * (t + 256 * j)) =
            *reinterpret_cast<const uint2*>(h);
    }
}

// ================= pipelined fp16 WMMA NT GEMM (64x64 warp tiles) ================
// C[M,N] = sum_k A[m,k]*B[n,k]; fp16 in, fp32 accum via HMMA.
// Block 256(M) x 128(N) x 64(K); 8 warps as 4x2 grid of 64x64 tiles;
// 4-stage cp.async, 1 barrier/iter. MMA:LDSM = 16:8 per warp-k-step.
// MODE 0: f32 out. MODE 1: fp16 out. MODE 2: f32 + bias out.
constexpr int BM = 256, BN = 128, BK = 64;
constexpr int PITCH = 72;                       // BK + 8 pad (halfs) = 144 B/row
constexpr int PLA = BM * PITCH * 2;             // A tile bytes = 36864
constexpr int PLB = BN * PITCH * 2;             // B tile bytes = 18432
constexpr int STAGEB = PLA + PLB;               // 55296 B
constexpr int STAGES = 4;
constexpr unsigned GSMEM = STAGES * STAGEB;     // 221184 B -> 1 CTA/SM

template <int MODE>
__global__ void __launch_bounds__(256) gemm_h(
    const __half* __restrict__ A, int lda, size_t strA,
    const __half* __restrict__ Bm, int ldb, size_t strB,
    void* __restrict__ C, int ldc, size_t strC,
    const float* __restrict__ bias, int Kdim) {
    extern __shared__ __half smem[];
    const uint32_t sbase = smem_u32(smem);
    const int tid = threadIdx.x;
    const int lane = tid & 31, wid = tid >> 5;
    const int wm = wid >> 1;                 // 0..3  (64-row strips)
    const int wn = wid & 1;                  // 0..1  (64-col strips)
    const int b = blockIdx.z;
    const int m0 = blockIdx.y * BM, n0 = blockIdx.x * BN;

    const __half* Ab = A + (size_t)b * strA;
    const __half* Bb = Bm + (size_t)b * strB;

    const int niter = Kdim / BK;

    // stage loader: A 256x64 (2048 chunks), B 128x64 (1024 chunks), 16B cp.async
    auto load_stage = [&](int j) {
        const int k0 = j * BK;
        const uint32_t sb = sbase + (j % STAGES) * STAGEB;
#pragma unroll
        for (int it = 0; it < 8; it++) {
            int id = tid + it * 256;             // 2048 chunks
            int r = id >> 3, c = id & 7;         // 256 rows x 8 x 16B
            uint32_t dst = sb + (uint32_t)(r * (PITCH * 2) + c * 16);
            cp16(dst, Ab + (size_t)(m0 + r) * lda + k0 + c * 8);
        }
#pragma unroll
        for (int it = 0; it < 4; it++) {
            int id = tid + it * 256;             // 1024 chunks
            int r = id >> 3, c = id & 7;         // 128 rows x 8 x 16B
            uint32_t dst = sb + (uint32_t)PLA + (uint32_t)(r * (PITCH * 2) + c * 16);
            cp16(dst, Bb + (size_t)(n0 + r) * ldb + k0 + c * 8);
        }
    };

    wmma::fragment<wmma::accumulator, 16, 16, 16, float> acc[4][4];
#pragma unroll
    for (int i = 0; i < 4; i++)
#pragma unroll
        for (int j = 0; j < 4; j++) wmma::fill_fragment(acc[i][j], 0.f);

    // prologue: 3 stages in flight
    load_stage(0); cp_commit();
    load_stage(1); cp_commit();
    load_stage(2); cp_commit();

    for (int i = 0; i < niter; i++) {
        cp_wait2();          // stage i resident (i+1, i+2 may be in flight)
        __syncthreads();     // stage i visible + all warps done computing i-1

        // prefetch stage i+3 into buffer (i+3)%4 = (i-1)%4 (dead past the barrier)
        if (i + 3 < niter) load_stage(i + 3);
        cp_commit();

        // compute stage i
        const __half* As = smem + (size_t)(i % STAGES) * (STAGEB / 2);
        const __half* Bs = As + PLA / 2;

#pragma unroll
        for (int kk = 0; kk < BK; kk += 16) {
            wmma::fragment<wmma::matrix_a, 16, 16, 16, __half, wmma::row_major> af[4];
#pragma unroll
            for (int x = 0; x < 4; x++) {
                int row = wm * 64 + x * 16;
                wmma::load_matrix_sync(af[x], As + row * PITCH + kk, PITCH);
            }
#pragma unroll
            for (int y = 0; y < 4; y++) {
                int col = wn * 64 + y * 16;
                wmma::fragment<wmma::matrix_b, 16, 16, 16, __half, wmma::col_major> bf;
                wmma::load_matrix_sync(bf, Bs + col * PITCH + kk, PITCH);
#pragma unroll
                for (int x = 0; x < 4; x++)
                    wmma::mma_sync(acc[x][y], af[x], bf, acc[x][y]);
            }
        }
        // no trailing barrier: next iteration's top barrier provides the ordering
    }

    __syncthreads();   // all compute done before epilogue reuses stage smem

    // ---------------- epilogue ----------------
    if (MODE == 0) {
        float* Cb = reinterpret_cast<float*>(C) + (size_t)b * strC;
#pragma unroll
        for (int x = 0; x < 4; x++)
#pragma unroll
            for (int y = 0; y < 4; y++) {
                int gr = m0 + wm * 64 + x * 16;
                int gc = n0 + wn * 64 + y * 16;
                wmma::store_matrix_sync(Cb + (size_t)gr * ldc + gc, acc[x][y], ldc,
                                        wmma::mem_row_major);
            }
    } else {
        // per-warp 16x72 f32 staging slab
        float* stage = reinterpret_cast<float*>(smem) + wid * (16 * 72);
        int wr0 = m0 + wm * 64, wc0 = n0 + wn * 64;
#pragma unroll
        for (int x = 0; x < 4; x++) {
#pragma unroll
            for (int y = 0; y < 4; y++)
                wmma::store_matrix_sync(stage + y * 16, acc[x][y], 72, wmma::mem_row_major);
            __syncwarp();
#pragma unroll
            for (int it = 0; it < 8; it++) {
                int idx = lane + it * 32;
                int r = idx >> 4, c = (idx & 15) << 2;
                float4 v = *reinterpret_cast<float4*>(stage + r * 72 + c);
                int gr = wr0 + x * 16 + r, gc = wc0 + c;
                if (MODE == 2) {
                    v.x += bias[gc]; v.y += bias[gc + 1];
                    v.z += bias[gc + 2]; v.w += bias[gc + 3];
                    float* Cb = reinterpret_cast<float*>(C);
                    *reinterpret_cast<float4*>(Cb + (size_t)gr * ldc + gc) = v;
                } else {  // MODE 1: fp16 out
                    __half* Cb = reinterpret_cast<__half*>(C) + (size_t)b * strC;
                    __half h[4] = {__float2half_rn(v.x), __float2half_rn(v.y),
                                   __float2half_rn(v.z), __float2half_rn(v.w)};
                    *reinterpret_cast<uint2*>(Cb + (size_t)gr * ldc + gc) =
                        *reinterpret_cast<const uint2*>(h);
                }
            }
            __syncwarp();
        }
    }
}

// ================= launch =================
extern "C" void kernel_launch(void* const* d_in, const int* in_sizes, int n_in,
                              void* d_out, int out_size) {
    const float* Q    = (const float*)d_in[0];
    const float* Kx   = (const float*)d_in[1];
    const float* V    = (const float*)d_in[2];
    const float* mask = (const float*)d_in[3];
    const float* W    = (const float*)d_in[4];
    const float* bias = (const float*)d_in[5];
    const int*   inv  = (const int*)d_in[6];

    void *pQ, *pK, *pVt, *pW, *pS, *pP, *pA;
    cudaGetSymbolAddress(&pQ, g_Qh);
    cudaGetSymbolAddress(&pK, g_Kh);
    cudaGetSymbolAddress(&pVt, g_Vt);
    cudaGetSymbolAddress(&pW, g_Wh);
    cudaGetSymbolAddress(&pS, g_scores);
    cudaGetSymbolAddress(&pP, g_P);
    cudaGetSymbolAddress(&pA, g_At);

    __half *Qh = (__half*)pQ, *Kh = (__half*)pK, *Vt = (__half*)pVt, *Wh = (__half*)pW;
    float* Sc = (float*)pS;
    __half *P = (__half*)pP, *At = (__half*)pA;

    cudaFuncSetAttribute(gemm_h<0>, cudaFuncAttributeMaxDynamicSharedMemorySize, GSMEM);
    cudaFuncSetAttribute(gemm_h<1>, cudaFuncAttributeMaxDynamicSharedMemorySize, GSMEM);
    cudaFuncSetAttribute(gemm_h<2>, cudaFuncAttributeMaxDynamicSharedMemorySize, GSMEM);

    const int n8 = B_ * S_ * E_ / 8;
    const int w8 = E_ * E_ / 8;

    // launch order keeps GEMM1 at index 3 (the ncu capture slot)
    cvt_half<<<(n8 + 255) / 256, 256>>>(Q, Qh, n8);            // 0
    cvt_half<<<(n8 + 255) / 256, 256>>>(Kx, Kh, n8);           // 1
    cvt_half<<<(w8 + 255) / 256, 256>>>(W, Wh, w8);            // 2

    // GEMM1: scores = Q @ K^T  [M=S, N=S, K=E]                   3
    dim3 g1(S_ / BN, S_ / BM, B_);
    gemm_h<0><<<g1, 256, GSMEM>>>(Qh, E_, (size_t)S_ * E_,
                                  Kh, E_, (size_t)S_ * E_,
                                  Sc, S_, (size_t)S_ * S_, nullptr, E_);

    // V transpose (needed only by GEMM2)                          4
    dim3 gt(S_ / 32, E_ / 32, B_);
    transpose_v<<<gt, 256>>>(V, Vt);

    // softmax * mask -> fp16 probs                                5
    softmax_mask_kernel<<<B_ * S_, 256>>>(Sc, mask, P, inv);

    // GEMM2: attn = P @ Vt^T   [M=S, N=E, K=S]                    6
    dim3 g2(E_ / BN, S_ / BM, B_);
    gemm_h<1><<<g2, 256, GSMEM>>>(P, S_, (size_t)S_ * S_,
                                  Vt, S_, (size_t)E_ * S_,
                                  At, E_, (size_t)S_ * E_, nullptr, S_);

    // GEMM3: out = attn @ W^T + bias  [M=B*S, N=E, K=E]           7
    dim3 g3(E_ / BN, (B_ * S_) / BM, 1);
    gemm_h<2><<<g3, 256, GSMEM>>>(At, E_, 0,
                                  Wh, E_, 0,
                                  d_out, E_, 0, bias, E_);
}

// round 15
// speedup vs baseline: 3.7546x; 1.0184x over previous
#include <cuda_runtime.h>
#include <cuda_fp16.h>
#include <cstdint>
#include <cstddef>
#include <mma.h>

using namespace nvcuda;

#define B_ 8
#define S_ 2048
#define E_ 1024

// ================= scratch (device globals; allocation-free rule) =================
__device__ __half g_Qh[(size_t)B_ * S_ * E_];
__device__ __half g_Kh[(size_t)B_ * S_ * E_];
__device__ __half g_Vh[(size_t)B_ * S_ * E_];   // V as-is [B,S,E] fp16 (NN GEMM2)
__device__ __half g_Wh[(size_t)E_ * E_];
__device__ float  g_scores[(size_t)B_ * S_ * S_];
__device__ __half g_P[(size_t)B_ * S_ * S_];
__device__ __half g_At[(size_t)B_ * S_ * E_];   // attn fp16

// ================= async-copy helpers =================
__device__ __forceinline__ uint32_t smem_u32(const void* p) {
    uint32_t a;
    asm("{ .reg .u64 t; cvta.to.shared.u64 t, %1; cvt.u32.u64 %0, t; }" : "=r"(a) : "l"(p));
    return a;
}
__device__ __forceinline__ void cp16(uint32_t dst, const void* src) {
    asm volatile("cp.async.cg.shared.global [%0], [%1], 16;" :: "r"(dst), "l"(src) : "memory");
}
__device__ __forceinline__ void cp_commit() { asm volatile("cp.async.commit_group;" ::: "memory"); }
__device__ __forceinline__ void cp_wait2()  { asm volatile("cp.async.wait_group 2;" ::: "memory"); }

// ================= prep kernels =================
__global__ void __launch_bounds__(256) cvt_half(const float* __restrict__ x,
                                                __half* __restrict__ y, int n8) {
    int i = blockIdx.x * blockDim.x + threadIdx.x;
    if (i >= n8) return;
    const float4* x4 = reinterpret_cast<const float4*>(x) + (size_t)i * 2;
    float4 a = x4[0], b = x4[1];
    float f[8] = {a.x, a.y, a.z, a.w, b.x, b.y, b.z, b.w};
    __half h[8];
#pragma unroll
    for (int j = 0; j < 8; j++) h[j] = __float2half_rn(f[j]);
    *reinterpret_cast<uint4*>(y + (size_t)i * 8) = *reinterpret_cast<const uint4*>(h);
}

// ================= softmax * mask -> fp16 probs =================
__global__ void __launch_bounds__(256) softmax_mask_kernel(
    const float* __restrict__ scores, const float* __restrict__ mask,
    __half* __restrict__ probs, const int* __restrict__ sc) {
    __shared__ float redmax[8], redsum[8];
    size_t row = blockIdx.x;
    const float4* srow = reinterpret_cast<const float4*>(scores + row * (size_t)S_);
    const float4* mrow = reinterpret_cast<const float4*>(mask + row * (size_t)S_);
    int t = threadIdx.x, lane = t & 31, warp = t >> 5;

    int iv = *sc;
    float denom = (iv == 32) ? 32.0f : __int_as_float(iv);
    float scale = 1.0f / denom;

    float v[8];
#pragma unroll
    for (int j = 0; j < 2; j++) {
        float4 x = srow[t + 256 * j];
        v[4 * j + 0] = x.x * scale; v[4 * j + 1] = x.y * scale;
        v[4 * j + 2] = x.z * scale; v[4 * j + 3] = x.w * scale;
    }
    float m = v[0];
#pragma unroll
    for (int j = 1; j < 8; j++) m = fmaxf(m, v[j]);
#pragma unroll
    for (int o = 16; o; o >>= 1) m = fmaxf(m, __shfl_xor_sync(0xffffffffu, m, o));
    if (lane == 0) redmax[warp] = m;
    __syncthreads();
    float bm = redmax[0];
#pragma unroll
    for (int w = 1; w < 8; w++) bm = fmaxf(bm, redmax[w]);
    float e[8], s = 0.f;
#pragma unroll
    for (int j = 0; j < 8; j++) { e[j] = __expf(v[j] - bm); s += e[j]; }
#pragma unroll
    for (int o = 16; o; o >>= 1) s += __shfl_xor_sync(0xffffffffu, s, o);
    if (lane == 0) redsum[warp] = s;
    __syncthreads();
    float bs = 0.f;
#pragma unroll
    for (int w = 0; w < 8; w++) bs += redsum[w];
    float inv = 1.0f / bs;

    __half* prow = probs + row * (size_t)S_;
#pragma unroll
    for (int j = 0; j < 2; j++) {
        float4 mk = mrow[t + 256 * j];
        float mf[4] = {mk.x, mk.y, mk.z, mk.w};
        __half h[4];
#pragma unroll
        for (int q = 0; q < 4; q++)
            h[q] = __float2half_rn(e[4 * j + q] * inv * mf[q]);
        *reinterpret_cast<uint2*>(prow + 4 * (t + 256 * j)) =
            *reinterpret_cast<const uint2*>(h);
    }
}

// ================= pipelined fp16 WMMA GEMM (64x64 warp tiles, A-frag DB) ========
// BT=true : C = A * B^T (B[n,k], col_major frags)  -- GEMM1, GEMM3
// BT=false: C = A * B   (B[k,n], row_major frags)  -- GEMM2 (V untransposed)
// Block 256(M) x 128(N) x 64(K); 8 warps as 4x2 grid of 64x64 tiles;
// 4-stage cp.async, 1 barrier/iter; A fragments double-buffered across k-steps.
// MODE 0: f32 out. MODE 1: fp16 out. MODE 2: f32 + bias out.
constexpr int BM = 256, BN = 128, BK = 64;
constexpr int PITCHA = 72;                      // BK + 8 halfs (NT rows / A rows)
constexpr int PITCHB_NN = 136;                  // BN + 8 halfs (NN B rows)
constexpr int PLA = BM * PITCHA * 2;            // A tile bytes = 36864
constexpr int PLB = 18432;                      // max(128*144, 64*272) = 18432 B
constexpr int STAGEB = PLA + PLB;               // 55296 B
constexpr int STAGES = 4;
constexpr unsigned GSMEM = STAGES * STAGEB;     // 221184 B -> 1 CTA/SM

template <int MODE, bool BT>
__global__ void __launch_bounds__(256) gemm_h(
    const __half* __restrict__ A, int lda, size_t strA,
    const __half* __restrict__ Bm, int ldb, size_t strB,
    void* __restrict__ C, int ldc, size_t strC,
    const float* __restrict__ bias, int Kdim) {
    extern __shared__ __half smem[];
    const uint32_t sbase = smem_u32(smem);
    const int tid = threadIdx.x;
    const int lane = tid & 31, wid = tid >> 5;
    const int wm = wid >> 1;                 // 0..3  (64-row strips)
    const int wn = wid & 1;                  // 0..1  (64-col strips)
    const int b = blockIdx.z;
    const int m0 = blockIdx.y * BM, n0 = blockIdx.x * BN;

    const __half* Ab = A + (size_t)b * strA;
    const __half* Bb = Bm + (size_t)b * strB;

    const int niter = Kdim / BK;

    // stage loader
    auto load_stage = [&](int j) {
        const int k0 = j * BK;
        const uint32_t sb = sbase + (j % STAGES) * STAGEB;
        // A: 256 rows x 64 halfs (128B/row), 2048 chunks
#pragma unroll
        for (int it = 0; it < 8; it++) {
            int id = tid + it * 256;
            int r = id >> 3, c = id & 7;
            uint32_t dst = sb + (uint32_t)(r * (PITCHA * 2) + c * 16);
            cp16(dst, Ab + (size_t)(m0 + r) * lda + k0 + c * 8);
        }
        if (BT) {
            // B: 128 rows (n) x 64 halfs (k), 1024 chunks
#pragma unroll
            for (int it = 0; it < 4; it++) {
                int id = tid + it * 256;
                int r = id >> 3, c = id & 7;
                uint32_t dst = sb + (uint32_t)PLA + (uint32_t)(r * (PITCHA * 2) + c * 16);
                cp16(dst, Bb + (size_t)(n0 + r) * ldb + k0 + c * 8);
            }
        } else {
            // B: 64 rows (k) x 128 halfs (n), 1024 chunks
#pragma unroll
            for (int it = 0; it < 4; it++) {
                int id = tid + it * 256;
                int r = id >> 4, c = id & 15;
                uint32_t dst = sb + (uint32_t)PLA + (uint32_t)(r * (PITCHB_NN * 2) + c * 16);
                cp16(dst, Bb + (size_t)(k0 + r) * ldb + n0 + c * 8);
            }
        }
    };

    wmma::fragment<wmma::accumulator, 16, 16, 16, float> acc[4][4];
#pragma unroll
    for (int i = 0; i < 4; i++)
#pragma unroll
        for (int j = 0; j < 4; j++) wmma::fill_fragment(acc[i][j], 0.f);

    // prologue: 3 stages in flight
    load_stage(0); cp_commit();
    load_stage(1); cp_commit();
    load_stage(2); cp_commit();

    wmma::fragment<wmma::matrix_a, 16, 16, 16, __half, wmma::row_major> af[2][4];

    for (int i = 0; i < niter; i++) {
        cp_wait2();          // stage i resident (i+1, i+2 may be in flight)
        __syncthreads();     // stage i visible + all warps done computing i-1

        // prefetch stage i+3 into buffer (i+3)%4 = (i-1)%4 (dead past the barrier)
        if (i + 3 < niter) load_stage(i + 3);
        cp_commit();

        const __half* As = smem + (size_t)(i % STAGES) * (STAGEB / 2);
        const __half* Bs = As + PLA / 2;

        // prime A fragments for kk = 0
#pragma unroll
        for (int x = 0; x < 4; x++)
            wmma::load_matrix_sync(af[0][x], As + (wm * 64 + x * 16) * PITCHA, PITCHA);

#pragma unroll
        for (int kk = 0; kk < BK; kk += 16) {
            const int cur = (kk >> 4) & 1;
            if (kk + 16 < BK) {
                // prefetch next k-step's A fragments (hides LDSM under MMAs)
#pragma unroll
                for (int x = 0; x < 4; x++)
                    wmma::load_matrix_sync(af[cur ^ 1][x],
                        As + (wm * 64 + x * 16) * PITCHA + kk + 16, PITCHA);
            }
#pragma unroll
            for (int y = 0; y < 4; y++) {
                int col = wn * 64 + y * 16;
                if (BT) {
                    wmma::fragment<wmma::matrix_b, 16, 16, 16, __half, wmma::col_major> bf;
                    wmma::load_matrix_sync(bf, Bs + col * PITCHA + kk, PITCHA);
#pragma unroll
                    for (int x = 0; x < 4; x++)
                        wmma::mma_sync(acc[x][y], af[cur][x], bf, acc[x][y]);
                } else {
                    wmma::fragment<wmma::matrix_b, 16, 16, 16, __half, wmma::row_major> bf;
                    wmma::load_matrix_sync(bf, Bs + kk * PITCHB_NN + col, PITCHB_NN);
#pragma unroll
                    for (int x = 0; x < 4; x++)
                        wmma::mma_sync(acc[x][y], af[cur][x], bf, acc[x][y]);
                }
            }
        }
        // no trailing barrier: next iteration's top barrier provides the ordering
    }

    __syncthreads();   // all compute done before epilogue reuses stage smem

    // ---------------- epilogue ----------------
    if (MODE == 0) {
        float* Cb = reinterpret_cast<float*>(C) + (size_t)b * strC;
#pragma unroll
        for (int x = 0; x < 4; x++)
#pragma unroll
            for (int y = 0; y < 4; y++) {
                int gr = m0 + wm * 64 + x * 16;
                int gc = n0 + wn * 64 + y * 16;
                wmma::store_matrix_sync(Cb + (size_t)gr * ldc + gc, acc[x][y], ldc,
                                        wmma::mem_row_major);
            }
    } else {
        float* stage = reinterpret_cast<float*>(smem) + wid * (16 * 72);
        int wr0 = m0 + wm * 64, wc0 = n0 + wn * 64;
#pragma unroll
        for (int x = 0; x < 4; x++) {
#pragma unroll
            for (int y = 0; y < 4; y++)
                wmma::store_matrix_sync(stage + y * 16, acc[x][y], 72, wmma::mem_row_major);
            __syncwarp();
#pragma unroll
            for (int it = 0; it < 8; it++) {
                int idx = lane + it * 32;
                int r = idx >> 4, c = (idx & 15) << 2;
                float4 v = *reinterpret_cast<float4*>(stage + r * 72 + c);
                int gr = wr0 + x * 16 + r, gc = wc0 + c;
                if (MODE == 2) {
                    v.x += bias[gc]; v.y += bias[gc + 1];
                    v.z += bias[gc + 2]; v.w += bias[gc + 3];
                    float* Cb = reinterpret_cast<float*>(C);
                    *reinterpret_cast<float4*>(Cb + (size_t)gr * ldc + gc) = v;
                } else {  // MODE 1: fp16 out
                    __half* Cb = reinterpret_cast<__half*>(C) + (size_t)b * strC;
                    __half h[4] = {__float2half_rn(v.x), __float2half_rn(v.y),
                                   __float2half_rn(v.z), __float2half_rn(v.w)};
                    *reinterpret_cast<uint2*>(Cb + (size_t)gr * ldc + gc) =
                        *reinterpret_cast<const uint2*>(h);
                }
            }
            __syncwarp();
        }
    }
}

// ================= launch =================
extern "C" void kernel_launch(void* const* d_in, const int* in_sizes, int n_in,
                              void* d_out, int out_size) {
    const float* Q    = (const float*)d_in[0];
    const float* Kx   = (const float*)d_in[1];
    const float* V    = (const float*)d_in[2];
    const float* mask = (const float*)d_in[3];
    const float* W    = (const float*)d_in[4];
    const float* bias = (const float*)d_in[5];
    const int*   inv  = (const int*)d_in[6];

    void *pQ, *pK, *pV, *pW, *pS, *pP, *pA;
    cudaGetSymbolAddress(&pQ, g_Qh);
    cudaGetSymbolAddress(&pK, g_Kh);
    cudaGetSymbolAddress(&pV, g_Vh);
    cudaGetSymbolAddress(&pW, g_Wh);
    cudaGetSymbolAddress(&pS, g_scores);
    cudaGetSymbolAddress(&pP, g_P);
    cudaGetSymbolAddress(&pA, g_At);

    __half *Qh = (__half*)pQ, *Kh = (__half*)pK, *Vh = (__half*)pV, *Wh = (__half*)pW;
    float* Sc = (float*)pS;
    __half *P = (__half*)pP, *At = (__half*)pA;

    cudaFuncSetAttribute((const void*)gemm_h<0, true>,
                         cudaFuncAttributeMaxDynamicSharedMemorySize, GSMEM);
    cudaFuncSetAttribute((const void*)gemm_h<1, false>,
                         cudaFuncAttributeMaxDynamicSharedMemorySize, GSMEM);
    cudaFuncSetAttribute((const void*)gemm_h<2, true>,
                         cudaFuncAttributeMaxDynamicSharedMemorySize, GSMEM);

    const int n8 = B_ * S_ * E_ / 8;
    const int w8 = E_ * E_ / 8;

    // launch order keeps GEMM1 at index 3 (the ncu capture slot)
    cvt_half<<<(n8 + 255) / 256, 256>>>(Q, Qh, n8);            // 0
    cvt_half<<<(n8 + 255) / 256, 256>>>(Kx, Kh, n8);           // 1
    cvt_half<<<(w8 + 255) / 256, 256>>>(W, Wh, w8);            // 2

    // GEMM1: scores = Q @ K^T  [M=S, N=S, K=E]                   3
    dim3 g1(S_ / BN, S_ / BM, B_);
    gemm_h<0, true><<<g1, 256, GSMEM>>>(Qh, E_, (size_t)S_ * E_,
                                        Kh, E_, (size_t)S_ * E_,
                                        Sc, S_, (size_t)S_ * S_, nullptr, E_);

    // V convert (no transpose; GEMM2 is NN)                       4
    cvt_half<<<(n8 + 255) / 256, 256>>>(V, Vh, n8);

    // softmax * mask -> fp16 probs                                5
    softmax_mask_kernel<<<B_ * S_, 256>>>(Sc, mask, P, inv);

    // GEMM2: attn = P @ V   [M=S, N=E, K=S]  (NN)                 6
    dim3 g2(E_ / BN, S_ / BM, B_);
    gemm_h<1, false><<<g2, 256, GSMEM>>>(P, S_, (size_t)S_ * S_,
                                         Vh, E_, (size_t)S_ * E_,
                                         At, E_, (size_t)S_ * E_, nullptr, S_);

    // GEMM3: out = attn @ W^T + bias  [M=B*S, N=E, K=E]           7
    dim3 g3(E_ / BN, (B_ * S_) / BM, 1);
    gemm_h<2, true><<<g3, 256, GSMEM>>>(At, E_, 0,
                                        Wh, E_, 0,
                                        d_out, E_, 0, bias, E_);
}

// round 16
// speedup vs baseline: 3.8657x; 1.0296x over previous
#include <cuda_runtime.h>
#include <cuda_fp16.h>
#include <cstdint>
#include <cstddef>
#include <mma.h>

using namespace nvcuda;

#define B_ 8
#define S_ 2048
#define E_ 1024

// ================= scratch (device globals; allocation-free rule) =================
__device__ __half g_Qh[(size_t)B_ * S_ * E_];
__device__ __half g_Kh[(size_t)B_ * S_ * E_];
__device__ __half g_Vh[(size_t)B_ * S_ * E_];   // V as-is [B,S,E] fp16 (NN GEMM2)
__device__ __half g_Wh[(size_t)E_ * E_];
__device__ float  g_scores[(size_t)B_ * S_ * S_];
__device__ __half g_P[(size_t)B_ * S_ * S_];
__device__ __half g_At[(size_t)B_ * S_ * E_];   // attn fp16

// ================= async-copy helpers =================
__device__ __forceinline__ uint32_t smem_u32(const void* p) {
    uint32_t a;
    asm("{ .reg .u64 t; cvta.to.shared.u64 t, %1; cvt.u32.u64 %0, t; }" : "=r"(a) : "l"(p));
    return a;
}
__device__ __forceinline__ void cp16(uint32_t dst, const void* src) {
    asm volatile("cp.async.cg.shared.global [%0], [%1], 16;" :: "r"(dst), "l"(src) : "memory");
}
__device__ __forceinline__ void cp_commit() { asm volatile("cp.async.commit_group;" ::: "memory"); }
__device__ __forceinline__ void cp_wait0()  { asm volatile("cp.async.wait_group 0;" ::: "memory"); }

// ================= prep kernels =================
__global__ void __launch_bounds__(256) cvt_half(const float* __restrict__ x,
                                                __half* __restrict__ y, int n8) {
    int i = blockIdx.x * blockDim.x + threadIdx.x;
    if (i >= n8) return;
    const float4* x4 = reinterpret_cast<const float4*>(x) + (size_t)i * 2;
    float4 a = x4[0], b = x4[1];
    float f[8] = {a.x, a.y, a.z, a.w, b.x, b.y, b.z, b.w};
    __half h[8];
#pragma unroll
    for (int j = 0; j < 8; j++) h[j] = __float2half_rn(f[j]);
    *reinterpret_cast<uint4*>(y + (size_t)i * 8) = *reinterpret_cast<const uint4*>(h);
}

// ================= softmax * mask -> fp16 probs =================
__global__ void __launch_bounds__(256) softmax_mask_kernel(
    const float* __restrict__ scores, const float* __restrict__ mask,
    __half* __restrict__ probs, const int* __restrict__ sc) {
    __shared__ float redmax[8], redsum[8];
    size_t row = blockIdx.x;
    const float4* srow = reinterpret_cast<const float4*>(scores + row * (size_t)S_);
    const float4* mrow = reinterpret_cast<const float4*>(mask + row * (size_t)S_);
    int t = threadIdx.x, lane = t & 31, warp = t >> 5;

    int iv = *sc;
    float denom = (iv == 32) ? 32.0f : __int_as_float(iv);
    float scale = 1.0f / denom;

    float v[8];
#pragma unroll
    for (int j = 0; j < 2; j++) {
        float4 x = srow[t + 256 * j];
        v[4 * j + 0] = x.x * scale; v[4 * j + 1] = x.y * scale;
        v[4 * j + 2] = x.z * scale; v[4 * j + 3] = x.w * scale;
    }
    float m = v[0];
#pragma unroll
    for (int j = 1; j < 8; j++) m = fmaxf(m, v[j]);
#pragma unroll
    for (int o = 16; o; o >>= 1) m = fmaxf(m, __shfl_xor_sync(0xffffffffu, m, o));
    if (lane == 0) redmax[warp] = m;
    __syncthreads();
    float bm = redmax[0];
#pragma unroll
    for (int w = 1; w < 8; w++) bm = fmaxf(bm, redmax[w]);
    float e[8], s = 0.f;
#pragma unroll
    for (int j = 0; j < 8; j++) { e[j] = __expf(v[j] - bm); s += e[j]; }
#pragma unroll
    for (int o = 16; o; o >>= 1) s += __shfl_xor_sync(0xffffffffu, s, o);
    if (lane == 0) redsum[warp] = s;
    __syncthreads();
    float bs = 0.f;
#pragma unroll
    for (int w = 0; w < 8; w++) bs += redsum[w];
    float inv = 1.0f / bs;

    __half* prow = probs + row * (size_t)S_;
#pragma unroll
    for (int j = 0; j < 2; j++) {
        float4 mk = mrow[t + 256 * j];
        float mf[4] = {mk.x, mk.y, mk.z, mk.w};
        __half h[4];
#pragma unroll
        for (int q = 0; q < 4; q++)
            h[q] = __float2half_rn(e[4 * j + q] * inv * mf[q]);
        *reinterpret_cast<uint2*>(prow + 4 * (t + 256 * j)) =
            *reinterpret_cast<const uint2*>(h);
    }
}

// ================= pipelined fp16 WMMA GEMM (BK=128, 2-stage, 1 barrier/iter) ====
// BT=true : C = A * B^T (B[n,k], col_major frags)  -- GEMM1, GEMM3
// BT=false: C = A * B   (B[k,n], row_major frags)  -- GEMM2 (V untransposed)
// Block 256(M) x 128(N) x 128(K); 8 warps as 4x2 grid of 64x64 tiles;
// A fragments double-buffered across k-steps.
// MODE 0: f32 out. MODE 1: fp16 out. MODE 2: f32 + bias out.
constexpr int BM = 256, BN = 128, BK = 128;
constexpr int PITCHA = 136;                     // BK + 8 halfs = 272 B/row
constexpr int PITCHB_NN = 136;                  // BN + 8 halfs = 272 B/row
constexpr int PLA = BM * PITCHA * 2;            // A tile bytes = 69632
constexpr int PLB = 34816;                      // 128 rows x 272 B (both layouts)
constexpr int STAGEB = PLA + PLB;               // 104448 B
constexpr int STAGES = 2;
constexpr unsigned GSMEM = STAGES * STAGEB;     // 208896 B -> 1 CTA/SM

template <int MODE, bool BT>
__global__ void __launch_bounds__(256) gemm_h(
    const __half* __restrict__ A, int lda, size_t strA,
    const __half* __restrict__ Bm, int ldb, size_t strB,
    void* __restrict__ C, int ldc, size_t strC,
    const float* __restrict__ bias, int Kdim) {
    extern __shared__ __half smem[];
    const uint32_t sbase = smem_u32(smem);
    const int tid = threadIdx.x;
    const int lane = tid & 31, wid = tid >> 5;
    const int wm = wid >> 1;                 // 0..3  (64-row strips)
    const int wn = wid & 1;                  // 0..1  (64-col strips)
    const int b = blockIdx.z;
    const int m0 = blockIdx.y * BM, n0 = blockIdx.x * BN;

    const __half* Ab = A + (size_t)b * strA;
    const __half* Bb = Bm + (size_t)b * strB;

    const int niter = Kdim / BK;

    // stage loader: A 256x128 halfs (4096 chunks), B 128 rows x 272B (2048 chunks)
    auto load_stage = [&](int j) {
        const int k0 = j * BK;
        const uint32_t sb = sbase + (j % STAGES) * STAGEB;
#pragma unroll
        for (int it = 0; it < 16; it++) {
            int id = tid + it * 256;             // 4096 chunks
            int r = id >> 4, c = id & 15;        // 256 rows x 16 x 16B
            uint32_t dst = sb + (uint32_t)(r * (PITCHA * 2) + c * 16);
            cp16(dst, Ab + (size_t)(m0 + r) * lda + k0 + c * 8);
        }
        if (BT) {
#pragma unroll
            for (int it = 0; it < 8; it++) {
                int id = tid + it * 256;         // 2048 chunks
                int r = id >> 4, c = id & 15;    // 128 n-rows x 16 x 16B
                uint32_t dst = sb + (uint32_t)PLA + (uint32_t)(r * (PITCHA * 2) + c * 16);
                cp16(dst, Bb + (size_t)(n0 + r) * ldb + k0 + c * 8);
            }
        } else {
#pragma unroll
            for (int it = 0; it < 8; it++) {
                int id = tid + it * 256;         // 2048 chunks
                int r = id >> 4, c = id & 15;    // 128 k-rows x 16 x 16B
                uint32_t dst = sb + (uint32_t)PLA + (uint32_t)(r * (PITCHB_NN * 2) + c * 16);
                cp16(dst, Bb + (size_t)(k0 + r) * ldb + n0 + c * 8);
            }
        }
    };

    wmma::fragment<wmma::accumulator, 16, 16, 16, float> acc[4][4];
#pragma unroll
    for (int i = 0; i < 4; i++)
#pragma unroll
        for (int j = 0; j < 4; j++) wmma::fill_fragment(acc[i][j], 0.f);

    // prologue: 1 stage in flight
    load_stage(0); cp_commit();

    wmma::fragment<wmma::matrix_a, 16, 16, 16, __half, wmma::row_major> af[2][4];

    for (int i = 0; i < niter; i++) {
        cp_wait0();          // stage i resident
        __syncthreads();     // + all warps done computing i-1 -> buf (i+1)%2 free

        // issue load of stage i+1 (overlaps this iteration's compute)
        if (i + 1 < niter) load_stage(i + 1);
        cp_commit();

        const __half* As = smem + (size_t)(i % STAGES) * (STAGEB / 2);
        const __half* Bs = As + PLA / 2;

        // prime A fragments for kk = 0
#pragma unroll
        for (int x = 0; x < 4; x++)
            wmma::load_matrix_sync(af[0][x], As + (wm * 64 + x * 16) * PITCHA, PITCHA);

#pragma unroll
        for (int kk = 0; kk < BK; kk += 16) {
            const int cur = (kk >> 4) & 1;
            if (kk + 16 < BK) {
                // prefetch next k-step's A fragments
#pragma unroll
                for (int x = 0; x < 4; x++)
                    wmma::load_matrix_sync(af[cur ^ 1][x],
                        As + (wm * 64 + x * 16) * PITCHA + kk + 16, PITCHA);
            }
#pragma unroll
            for (int y = 0; y < 4; y++) {
                int col = wn * 64 + y * 16;
                if (BT) {
                    wmma::fragment<wmma::matrix_b, 16, 16, 16, __half, wmma::col_major> bf;
                    wmma::load_matrix_sync(bf, Bs + col * PITCHA + kk, PITCHA);
#pragma unroll
                    for (int x = 0; x < 4; x++)
                        wmma::mma_sync(acc[x][y], af[cur][x], bf, acc[x][y]);
                } else {
                    wmma::fragment<wmma::matrix_b, 16, 16, 16, __half, wmma::row_major> bf;
                    wmma::load_matrix_sync(bf, Bs + kk * PITCHB_NN + col, PITCHB_NN);
#pragma unroll
                    for (int x = 0; x < 4; x++)
                        wmma::mma_sync(acc[x][y], af[cur][x], bf, acc[x][y]);
                }
            }
        }
        // no trailing barrier: next iteration's top barrier provides the ordering
    }

    __syncthreads();   // all compute done before epilogue reuses stage smem

    // ---------------- epilogue ----------------
    if (MODE == 0) {
        float* Cb = reinterpret_cast<float*>(C) + (size_t)b * strC;
#pragma unroll
        for (int x = 0; x < 4; x++)
#pragma unroll
            for (int y = 0; y < 4; y++) {
                int gr = m0 + wm * 64 + x * 16;
                int gc = n0 + wn * 64 + y * 16;
                wmma::store_matrix_sync(Cb + (size_t)gr * ldc + gc, acc[x][y], ldc,
                                        wmma::mem_row_major);
            }
    } else {
        float* stage = reinterpret_cast<float*>(smem) + wid * (16 * 72);
        int wr0 = m0 + wm * 64, wc0 = n0 + wn * 64;
#pragma unroll
        for (int x = 0; x < 4; x++) {
#pragma unroll
            for (int y = 0; y < 4; y++)
                wmma::store_matrix_sync(stage + y * 16, acc[x][y], 72, wmma::mem_row_major);
            __syncwarp();
#pragma unroll
            for (int it = 0; it < 8; it++) {
                int idx = lane + it * 32;
                int r = idx >> 4, c = (idx & 15) << 2;
                float4 v = *reinterpret_cast<float4*>(stage + r * 72 + c);
                int gr = wr0 + x * 16 + r, gc = wc0 + c;
                if (MODE == 2) {
                    v.x += bias[gc]; v.y += bias[gc + 1];
                    v.z += bias[gc + 2]; v.w += bias[gc + 3];
                    float* Cb = reinterpret_cast<float*>(C);
                    *reinterpret_cast<float4*>(Cb + (size_t)gr * ldc + gc) = v;
                } else {  // MODE 1: fp16 out
                    __half* Cb = reinterpret_cast<__half*>(C) + (size_t)b * strC;
                    __half h[4] = {__float2half_rn(v.x), __float2half_rn(v.y),
                                   __float2half_rn(v.z), __float2half_rn(v.w)};
                    *reinterpret_cast<uint2*>(Cb + (size_t)gr * ldc + gc) =
                        *reinterpret_cast<const uint2*>(h);
                }
            }
            __syncwarp();
        }
    }
}

// ================= launch =================
extern "C" void kernel_launch(void* const* d_in, const int* in_sizes, int n_in,
                              void* d_out, int out_size) {
    const float* Q    = (const float*)d_in[0];
    const float* Kx   = (const float*)d_in[1];
    const float* V    = (const float*)d_in[2];
    const float* mask = (const float*)d_in[3];
    const float* W    = (const float*)d_in[4];
    const float* bias = (const float*)d_in[5];
    const int*   inv  = (const int*)d_in[6];

    void *pQ, *pK, *pV, *pW, *pS, *pP, *pA;
    cudaGetSymbolAddress(&pQ, g_Qh);
    cudaGetSymbolAddress(&pK, g_Kh);
    cudaGetSymbolAddress(&pV, g_Vh);
    cudaGetSymbolAddress(&pW, g_Wh);
    cudaGetSymbolAddress(&pS, g_scores);
    cudaGetSymbolAddress(&pP, g_P);
    cudaGetSymbolAddress(&pA, g_At);

    __half *Qh = (__half*)pQ, *Kh = (__half*)pK, *Vh = (__half*)pV, *Wh = (__half*)pW;
    float* Sc = (float*)pS;
    __half *P = (__half*)pP, *At = (__half*)pA;

    cudaFuncSetAttribute((const void*)gemm_h<0, true>,
                         cudaFuncAttributeMaxDynamicSharedMemorySize, GSMEM);
    cudaFuncSetAttribute((const void*)gemm_h<1, false>,
                         cudaFuncAttributeMaxDynamicSharedMemorySize, GSMEM);
    cudaFuncSetAttribute((const void*)gemm_h<2, true>,
                         cudaFuncAttributeMaxDynamicSharedMemorySize, GSMEM);

    const int n8 = B_ * S_ * E_ / 8;
    const int w8 = E_ * E_ / 8;

    // launch order keeps GEMM1 at index 3 (the ncu capture slot)
    cvt_half<<<(n8 + 255) / 256, 256>>>(Q, Qh, n8);            // 0
    cvt_half<<<(n8 + 255) / 256, 256>>>(Kx, Kh, n8);           // 1
    cvt_half<<<(w8 + 255) / 256, 256>>>(W, Wh, w8);            // 2

    // GEMM1: scores = Q @ K^T  [M=S, N=S, K=E]                   3
    dim3 g1(S_ / BN, S_ / BM, B_);
    gemm_h<0, true><<<g1, 256, GSMEM>>>(Qh, E_, (size_t)S_ * E_,
                                        Kh, E_, (size_t)S_ * E_,
                                        Sc, S_, (size_t)S_ * S_, nullptr, E_);

    // V convert (no transpose; GEMM2 is NN)                       4
    cvt_half<<<(n8 + 255) / 256, 256>>>(V, Vh, n8);

    // softmax * mask -> fp16 probs                                5
    softmax_mask_kernel<<<B_ * S_, 256>>>(Sc, mask, P, inv);

    // GEMM2: attn = P @ V   [M=S, N=E, K=S]  (NN)                 6
    dim3 g2(E_ / BN, S_ / BM, B_);
    gemm_h<1, false><<<g2, 256, GSMEM>>>(P, S_, (size_t)S_ * S_,
                                         Vh, E_, (size_t)S_ * E_,
                                         At, E_, (size_t)S_ * E_, nullptr, S_);

    // GEMM3: out = attn @ W^T + bias  [M=B*S, N=E, K=E]           7
    dim3 g3(E_ / BN, (B_ * S_) / BM, 1);
    gemm_h<2, true><<<g3, 256, GSMEM>>>(At, E_, 0,
                                        Wh, E_, 0,
                                        d_out, E_, 0, bias, E_);
}

// round 17
// speedup vs baseline: 3.9131x; 1.0123x over previous
#include <cuda_runtime.h>
#include <cuda_fp16.h>
#include <cstdint>
#include <cstddef>
#include <mma.h>

using namespace nvcuda;

#define B_ 8
#define S_ 2048
#define E_ 1024

// ================= scratch (device globals; allocation-free rule) =================
__device__ __half g_Qh[(size_t)B_ * S_ * E_];
__device__ __half g_Kh[(size_t)B_ * S_ * E_];
__device__ __half g_Vh[(size_t)B_ * S_ * E_];   // V as-is [B,S,E] fp16 (NN GEMM2)
__device__ __half g_Wh[(size_t)E_ * E_];
__device__ float  g_scores[(size_t)B_ * S_ * S_];
__device__ __half g_P[(size_t)B_ * S_ * S_];
__device__ __half g_At[(size_t)B_ * S_ * E_];   // attn fp16

// ================= async-copy helpers =================
__device__ __forceinline__ uint32_t smem_u32(const void* p) {
    uint32_t a;
    asm("{ .reg .u64 t; cvta.to.shared.u64 t, %1; cvt.u32.u64 %0, t; }" : "=r"(a) : "l"(p));
    return a;
}
__device__ __forceinline__ void cp16(uint32_t dst, const void* src) {
    asm volatile("cp.async.cg.shared.global [%0], [%1], 16;" :: "r"(dst), "l"(src) : "memory");
}
__device__ __forceinline__ void cp_commit() { asm volatile("cp.async.commit_group;" ::: "memory"); }
__device__ __forceinline__ void cp_wait0()  { asm volatile("cp.async.wait_group 0;" ::: "memory"); }
__device__ __forceinline__ void cp_wait1()  { asm volatile("cp.async.wait_group 1;" ::: "memory"); }

// ================= prep kernels =================
__global__ void __launch_bounds__(256) cvt_half(const float* __restrict__ x,
                                                __half* __restrict__ y, int n8) {
    int i = blockIdx.x * blockDim.x + threadIdx.x;
    if (i >= n8) return;
    const float4* x4 = reinterpret_cast<const float4*>(x) + (size_t)i * 2;
    float4 a = x4[0], b = x4[1];
    float f[8] = {a.x, a.y, a.z, a.w, b.x, b.y, b.z, b.w};
    __half h[8];
#pragma unroll
    for (int j = 0; j < 8; j++) h[j] = __float2half_rn(f[j]);
    *reinterpret_cast<uint4*>(y + (size_t)i * 8) = *reinterpret_cast<const uint4*>(h);
}

// ================= softmax * mask -> fp16 probs =================
__global__ void __launch_bounds__(256) softmax_mask_kernel(
    const float* __restrict__ scores, const float* __restrict__ mask,
    __half* __restrict__ probs, const int* __restrict__ sc) {
    __shared__ float redmax[8], redsum[8];
    size_t row = blockIdx.x;
    const float4* srow = reinterpret_cast<const float4*>(scores + row * (size_t)S_);
    const float4* mrow = reinterpret_cast<const float4*>(mask + row * (size_t)S_);
    int t = threadIdx.x, lane = t & 31, warp = t >> 5;

    int iv = *sc;
    float denom = (iv == 32) ? 32.0f : __int_as_float(iv);
    float scale = 1.0f / denom;

    float v[8];
#pragma unroll
    for (int j = 0; j < 2; j++) {
        float4 x = srow[t + 256 * j];
        v[4 * j + 0] = x.x * scale; v[4 * j + 1] = x.y * scale;
        v[4 * j + 2] = x.z * scale; v[4 * j + 3] = x.w * scale;
    }
    float m = v[0];
#pragma unroll
    for (int j = 1; j < 8; j++) m = fmaxf(m, v[j]);
#pragma unroll
    for (int o = 16; o; o >>= 1) m = fmaxf(m, __shfl_xor_sync(0xffffffffu, m, o));
    if (lane == 0) redmax[warp] = m;
    __syncthreads();
    float bm = redmax[0];
#pragma unroll
    for (int w = 1; w < 8; w++) bm = fmaxf(bm, redmax[w]);
    float e[8], s = 0.f;
#pragma unroll
    for (int j = 0; j < 8; j++) { e[j] = __expf(v[j] - bm); s += e[j]; }
#pragma unroll
    for (int o = 16; o; o >>= 1) s += __shfl_xor_sync(0xffffffffu, s, o);
    if (lane == 0) redsum[warp] = s;
    __syncthreads();
    float bs = 0.f;
#pragma unroll
    for (int w = 0; w < 8; w++) bs += redsum[w];
    float inv = 1.0f / bs;

    __half* prow = probs + row * (size_t)S_;
#pragma unroll
    for (int j = 0; j < 2; j++) {
        float4 mk = mrow[t + 256 * j];
        float mf[4] = {mk.x, mk.y, mk.z, mk.w};
        __half h[4];
#pragma unroll
        for (int q = 0; q < 4; q++)
            h[q] = __float2half_rn(e[4 * j + q] * inv * mf[q]);
        *reinterpret_cast<uint2*>(prow + 4 * (t + 256 * j)) =
            *reinterpret_cast<const uint2*>(h);
    }
}

// ====== EXPERIMENT: 2-CTA-per-SM fp16 NT GEMM (128x128x64, 3-stage) — GEMM1 only ==
constexpr int CBM = 128, CBN = 128, CBK = 64;
constexpr int CPITCH = 72;                      // 64 + 8 halfs = 144 B/row
constexpr int CPL = CBM * CPITCH * 2;           // 18432 B per operand tile
constexpr int CSTAGEB = 2 * CPL;                // 36864 B
constexpr int CSTAGES = 3;
constexpr unsigned CGSMEM = CSTAGES * CSTAGEB;  // 110592 B -> 2 CTAs/SM

__global__ void __launch_bounds__(256, 2) gemm_c(
    const __half* __restrict__ A, int lda, size_t strA,
    const __half* __restrict__ Bm, int ldb, size_t strB,
    float* __restrict__ C, int ldc, size_t strC, int Kdim) {
    extern __shared__ __half smem[];
    const uint32_t sbase = smem_u32(smem);
    const int tid = threadIdx.x;
    const int wid = tid >> 5;
    const int wm = wid >> 1;                 // 0..3 (32-row strips)
    const int wn = wid & 1;                  // 0..1 (64-col strips)
    const int b = blockIdx.z;
    const int m0 = blockIdx.y * CBM, n0 = blockIdx.x * CBN;

    const __half* Ab = A + (size_t)b * strA;
    const __half* Bb = Bm + (size_t)b * strB;

    const int niter = Kdim / CBK;

    auto load_stage = [&](int j) {
        const int k0 = j * CBK;
        const uint32_t sb = sbase + (j % CSTAGES) * CSTAGEB;
#pragma unroll
        for (int it = 0; it < 4; it++) {
            int id = tid + it * 256;             // 1024 chunks
            int r = id >> 3, c = id & 7;         // 128 rows x 8 x 16B
            uint32_t dst = sb + (uint32_t)(r * (CPITCH * 2) + c * 16);
            cp16(dst, Ab + (size_t)(m0 + r) * lda + k0 + c * 8);
        }
#pragma unroll
        for (int it = 0; it < 4; it++) {
            int id = tid + it * 256;
            int r = id >> 3, c = id & 7;
            uint32_t dst = sb + (uint32_t)CPL + (uint32_t)(r * (CPITCH * 2) + c * 16);
            cp16(dst, Bb + (size_t)(n0 + r) * ldb + k0 + c * 8);
        }
    };

    wmma::fragment<wmma::accumulator, 16, 16, 16, float> acc[2][4];
#pragma unroll
    for (int i = 0; i < 2; i++)
#pragma unroll
        for (int j = 0; j < 4; j++) wmma::fill_fragment(acc[i][j], 0.f);

    load_stage(0); cp_commit();
    load_stage(1); cp_commit();

    for (int i = 0; i < niter; i++) {
        cp_wait1();
        __syncthreads();

        if (i + 2 < niter) load_stage(i + 2);
        cp_commit();

        const __half* As = smem + (size_t)(i % CSTAGES) * (CSTAGEB / 2);
        const __half* Bs = As + CPL / 2;

#pragma unroll
        for (int kk = 0; kk < CBK; kk += 16) {
            wmma::fragment<wmma::matrix_a, 16, 16, 16, __half, wmma::row_major> af[2];
#pragma unroll
            for (int x = 0; x < 2; x++)
                wmma::load_matrix_sync(af[x], As + (wm * 32 + x * 16) * CPITCH + kk, CPITCH);
#pragma unroll
            for (int y = 0; y < 4; y++) {
                int col = wn * 64 + y * 16;
                wmma::fragment<wmma::matrix_b, 16, 16, 16, __half, wmma::col_major> bf;
                wmma::load_matrix_sync(bf, Bs + col * CPITCH + kk, CPITCH);
#pragma unroll
                for (int x = 0; x < 2; x++)
                    wmma::mma_sync(acc[x][y], af[x], bf, acc[x][y]);
            }
        }
        __syncthreads();   // compute done before prefetch overwrites (3-stage slack)
    }

    float* Cb = C + (size_t)b * strC;
#pragma unroll
    for (int x = 0; x < 2; x++)
#pragma unroll
        for (int y = 0; y < 4; y++) {
            int gr = m0 + wm * 32 + x * 16;
            int gc = n0 + wn * 64 + y * 16;
            wmma::store_matrix_sync(Cb + (size_t)gr * ldc + gc, acc[x][y], ldc,
                                    wmma::mem_row_major);
        }
}

// ================= champion fp16 WMMA GEMM (BK=128, 2-stage) — GEMM2/GEMM3 ======
constexpr int BM = 256, BN = 128, BK = 128;
constexpr int PITCHA = 136;                     // BK + 8 halfs = 272 B/row
constexpr int PITCHB_NN = 136;
constexpr int PLA = BM * PITCHA * 2;            // 69632
constexpr int PLB = 34816;
constexpr int STAGEB = PLA + PLB;               // 104448
constexpr int STAGES = 2;
constexpr unsigned GSMEM = STAGES * STAGEB;     // 208896 -> 1 CTA/SM

template <int MODE, bool BT>
__global__ void __launch_bounds__(256) gemm_h(
    const __half* __restrict__ A, int lda, size_t strA,
    const __half* __restrict__ Bm, int ldb, size_t strB,
    void* __restrict__ C, int ldc, size_t strC,
    const float* __restrict__ bias, int Kdim) {
    extern __shared__ __half smem[];
    const uint32_t sbase = smem_u32(smem);
    const int tid = threadIdx.x;
    const int lane = tid & 31, wid = tid >> 5;
    const int wm = wid >> 1;
    const int wn = wid & 1;
    const int b = blockIdx.z;
    const int m0 = blockIdx.y * BM, n0 = blockIdx.x * BN;

    const __half* Ab = A + (size_t)b * strA;
    const __half* Bb = Bm + (size_t)b * strB;

    const int niter = Kdim / BK;

    auto load_stage = [&](int j) {
        const int k0 = j * BK;
        const uint32_t sb = sbase + (j % STAGES) * STAGEB;
#pragma unroll
        for (int it = 0; it < 16; it++) {
            int id = tid + it * 256;
            int r = id >> 4, c = id & 15;
            uint32_t dst = sb + (uint32_t)(r * (PITCHA * 2) + c * 16);
            cp16(dst, Ab + (size_t)(m0 + r) * lda + k0 + c * 8);
        }
        if (BT) {
#pragma unroll
            for (int it = 0; it < 8; it++) {
                int id = tid + it * 256;
                int r = id >> 4, c = id & 15;
                uint32_t dst = sb + (uint32_t)PLA + (uint32_t)(r * (PITCHA * 2) + c * 16);
                cp16(dst, Bb + (size_t)(n0 + r) * ldb + k0 + c * 8);
            }
        } else {
#pragma unroll
            for (int it = 0; it < 8; it++) {
                int id = tid + it * 256;
                int r = id >> 4, c = id & 15;
                uint32_t dst = sb + (uint32_t)PLA + (uint32_t)(r * (PITCHB_NN * 2) + c * 16);
                cp16(dst, Bb + (size_t)(k0 + r) * ldb + n0 + c * 8);
            }
        }
    };

    wmma::fragment<wmma::accumulator, 16, 16, 16, float> acc[4][4];
#pragma unroll
    for (int i = 0; i < 4; i++)
#pragma unroll
        for (int j = 0; j < 4; j++) wmma::fill_fragment(acc[i][j], 0.f);

    load_stage(0); cp_commit();

    wmma::fragment<wmma::matrix_a, 16, 16, 16, __half, wmma::row_major> af[2][4];

    for (int i = 0; i < niter; i++) {
        cp_wait0();
        __syncthreads();

        if (i + 1 < niter) load_stage(i + 1);
        cp_commit();

        const __half* As = smem + (size_t)(i % STAGES) * (STAGEB / 2);
        const __half* Bs = As + PLA / 2;

#pragma unroll
        for (int x = 0; x < 4; x++)
            wmma::load_matrix_sync(af[0][x], As + (wm * 64 + x * 16) * PITCHA, PITCHA);

#pragma unroll
        for (int kk = 0; kk < BK; kk += 16) {
            const int cur = (kk >> 4) & 1;
            if (kk + 16 < BK) {
#pragma unroll
                for (int x = 0; x < 4; x++)
                    wmma::load_matrix_sync(af[cur ^ 1][x],
                        As + (wm * 64 + x * 16) * PITCHA + kk + 16, PITCHA);
            }
#pragma unroll
            for (int y = 0; y < 4; y++) {
                int col = wn * 64 + y * 16;
                if (BT) {
                    wmma::fragment<wmma::matrix_b, 16, 16, 16, __half, wmma::col_major> bf;
                    wmma::load_matrix_sync(bf, Bs + col * PITCHA + kk, PITCHA);
#pragma unroll
                    for (int x = 0; x < 4; x++)
                        wmma::mma_sync(acc[x][y], af[cur][x], bf, acc[x][y]);
                } else {
                    wmma::fragment<wmma::matrix_b, 16, 16, 16, __half, wmma::row_major> bf;
                    wmma::load_matrix_sync(bf, Bs + kk * PITCHB_NN + col, PITCHB_NN);
#pragma unroll
                    for (int x = 0; x < 4; x++)
                        wmma::mma_sync(acc[x][y], af[cur][x], bf, acc[x][y]);
                }
            }
        }
    }

    __syncthreads();

    if (MODE == 0) {
        float* Cb = reinterpret_cast<float*>(C) + (size_t)b * strC;
#pragma unroll
        for (int x = 0; x < 4; x++)
#pragma unroll
            for (int y = 0; y < 4; y++) {
                int gr = m0 + wm * 64 + x * 16;
                int gc = n0 + wn * 64 + y * 16;
                wmma::store_matrix_sync(Cb + (size_t)gr * ldc + gc, acc[x][y], ldc,
                                        wmma::mem_row_major);
            }
    } else {
        float* stage = reinterpret_cast<float*>(smem) + wid * (16 * 72);
        int wr0 = m0 + wm * 64, wc0 = n0 + wn * 64;
#pragma unroll
        for (int x = 0; x < 4; x++) {
#pragma unroll
            for (int y = 0; y < 4; y++)
                wmma::store_matrix_sync(stage + y * 16, acc[x][y], 72, wmma::mem_row_major);
            __syncwarp();
#pragma unroll
            for (int it = 0; it < 8; it++) {
                int idx = lane + it * 32;
                int r = idx >> 4, c = (idx & 15) << 2;
                float4 v = *reinterpret_cast<float4*>(stage + r * 72 + c);
                int gr = wr0 + x * 16 + r, gc = wc0 + c;
                if (MODE == 2) {
                    v.x += bias[gc]; v.y += bias[gc + 1];
                    v.z += bias[gc + 2]; v.w += bias[gc + 3];
                    float* Cb = reinterpret_cast<float*>(C);
                    *reinterpret_cast<float4*>(Cb + (size_t)gr * ldc + gc) = v;
                } else {
                    __half* Cb = reinterpret_cast<__half*>(C) + (size_t)b * strC;
                    __half h[4] = {__float2half_rn(v.x), __float2half_rn(v.y),
                                   __float2half_rn(v.z), __float2half_rn(v.w)};
                    *reinterpret_cast<uint2*>(Cb + (size_t)gr * ldc + gc) =
                        *reinterpret_cast<const uint2*>(h);
                }
            }
            __syncwarp();
        }
    }
}

// ================= launch =================
extern "C" void kernel_launch(void* const* d_in, const int* in_sizes, int n_in,
                              void* d_out, int out_size) {
    const float* Q    = (const float*)d_in[0];
    const float* Kx   = (const float*)d_in[1];
    const float* V    = (const float*)d_in[2];
    const float* mask = (const float*)d_in[3];
    const float* W    = (const float*)d_in[4];
    const float* bias = (const float*)d_in[5];
    const int*   inv  = (const int*)d_in[6];

    void *pQ, *pK, *pV, *pW, *pS, *pP, *pA;
    cudaGetSymbolAddress(&pQ, g_Qh);
    cudaGetSymbolAddress(&pK, g_Kh);
    cudaGetSymbolAddress(&pV, g_Vh);
    cudaGetSymbolAddress(&pW, g_Wh);
    cudaGetSymbolAddress(&pS, g_scores);
    cudaGetSymbolAddress(&pP, g_P);
    cudaGetSymbolAddress(&pA, g_At);

    __half *Qh = (__half*)pQ, *Kh = (__half*)pK, *Vh = (__half*)pV, *Wh = (__half*)pW;
    float* Sc = (float*)pS;
    __half *P = (__half*)pP, *At = (__half*)pA;

    cudaFuncSetAttribute((const void*)gemm_c,
                         cudaFuncAttributeMaxDynamicSharedMemorySize, CGSMEM);
    cudaFuncSetAttribute((const void*)gemm_h<1, false>,
                         cudaFuncAttributeMaxDynamicSharedMemorySize, GSMEM);
    cudaFuncSetAttribute((const void*)gemm_h<2, true>,
                         cudaFuncAttributeMaxDynamicSharedMemorySize, GSMEM);

    const int n8 = B_ * S_ * E_ / 8;
    const int w8 = E_ * E_ / 8;

    // launch order keeps GEMM1 at index 3 (the ncu capture slot)
    cvt_half<<<(n8 + 255) / 256, 256>>>(Q, Qh, n8);            // 0
    cvt_half<<<(n8 + 255) / 256, 256>>>(Kx, Kh, n8);           // 1
    cvt_half<<<(w8 + 255) / 256, 256>>>(W, Wh, w8);            // 2

    // GEMM1: scores = Q @ K^T  (2-CTA co-residency experiment)    3
    dim3 g1(S_ / CBN, S_ / CBM, B_);
    gemm_c<<<g1, 256, CGSMEM>>>(Qh, E_, (size_t)S_ * E_,
                                Kh, E_, (size_t)S_ * E_,
                                Sc, S_, (size_t)S_ * S_, E_);

    // V convert (no transpose; GEMM2 is NN)                       4
    cvt_half<<<(n8 + 255) / 256, 256>>>(V, Vh, n8);

    // softmax * mask -> fp16 probs                                5
    softmax_mask_kernel<<<B_ * S_, 256>>>(Sc, mask, P, inv);

    // GEMM2: attn = P @ V   [M=S, N=E, K=S]  (NN, champion)       6
    dim3 g2(E_ / BN, S_ / BM, B_);
    gemm_h<1, false><<<g2, 256, GSMEM>>>(P, S_, (size_t)S_ * S_,
                                         Vh, E_, (size_t)S_ * E_,
                                         At, E_, (size_t)S_ * E_, nullptr, S_);

    // GEMM3: out = attn @ W^T + bias  (champion)                  7
    dim3 g3(E_ / BN, (B_ * S_) / BM, 1);
    gemm_h<2, true><<<g3, 256, GSMEM>>>(At, E_, 0,
                                        Wh, E_, 0,
                                        d_out, E_, 0, bias, E_);
}